// round 9
// baseline (speedup 1.0000x reference)
#include <cuda_runtime.h>

#define NSTATE 65536
#define BMAX   1024

__device__ __align__(16) float g_state[(size_t)BMAX * NSTATE];

__device__ __forceinline__ unsigned long long pk2(float a, float b) {
  unsigned long long r;
  asm("mov.b64 %0, {%1, %2};" : "=l"(r) : "f"(a), "f"(b));
  return r;
}

// tan-form RY (packed): lo' = lo - t*hi ; hi' = hi + t*lo   (cos factored out)
template<int S2>
__device__ __forceinline__ void ry2t(float2* r, float t) {
  const unsigned long long t2 = pk2(t, t), nt2 = pk2(-t, -t);
#pragma unroll
  for (int base = 0; base < 32; base += 2 * S2)
#pragma unroll
    for (int k = 0; k < S2; k++) {
      unsigned long long lo = *(unsigned long long*)&r[base + k];
      unsigned long long hi = *(unsigned long long*)&r[base + k + S2];
      unsigned long long nlo, nhi;
      asm("fma.rn.f32x2 %0, %1, %2, %3;" : "=l"(nlo) : "l"(nt2), "l"(hi), "l"(lo));
      asm("fma.rn.f32x2 %0, %1, %2, %3;" : "=l"(nhi) : "l"(t2),  "l"(lo), "l"(hi));
      *(unsigned long long*)&r[base + k]      = nlo;
      *(unsigned long long*)&r[base + k + S2] = nhi;
    }
}

// tan-form RY inside each float2
__device__ __forceinline__ void ryct(float2* r, float t) {
#pragma unroll
  for (int i = 0; i < 32; i++) {
    float x = r[i].x, y = r[i].y;
    r[i].x = fmaf(-t, y, x);
    r[i].y = fmaf( t, x, y);
  }
}

__device__ __forceinline__ void scale32(float2* r, float c) {
  const unsigned long long c2 = pk2(c, c);
#pragma unroll
  for (int i = 0; i < 32; i++) {
    unsigned long long v = *(unsigned long long*)&r[i], o;
    asm("mul.rn.f32x2 %0, %1, %2;" : "=l"(o) : "l"(c2), "l"(v));
    *(unsigned long long*)&r[i] = o;
  }
}

template<int C2, int T2>
__device__ __forceinline__ void cnot2(float2* r) {
#pragma unroll
  for (int i = 0; i < 32; i++)
    if ((i & C2) && !(i & T2)) { float2 t = r[i]; r[i] = r[i | T2]; r[i | T2] = t; }
}
template<int C2>
__device__ __forceinline__ void cnotc(float2* r) {
#pragma unroll
  for (int i = 0; i < 32; i++)
    if (i & C2) { float t = r[i].x; r[i].x = r[i].y; r[i].y = t; }
}

#define TILE_F   2176                 // 32 rows * 68 floats (pad 4/row)
#define TILES_F  (8 * TILE_F)
#define SMEM_FLOATS (TILES_F + 128 + 128 + 128 + 16 + 16 + 16 + 64 + 64 + 16 + 16)
#define SMEM_BYTES  (SMEM_FLOATS * 4)

__global__ void __launch_bounds__(256, 2)
vqc_kernel(const float* __restrict__ x, const float* __restrict__ w,
           float* __restrict__ out)
{
  extern __shared__ float sm[];
  float* tiles = sm;
  float* wc  = sm + TILES_F;      // [8][16] cos(w/2)
  float* ws  = wc + 128;          // [8][16] sin(w/2)
  float* wt  = ws + 128;          // [8][16] tan(w/2)
  float* CS  = wt + 128;          // [8] per-layer cos-product scale
  float* eA0 = CS + 16;           // [16]
  float* eA1 = eA0 + 16;          // [16]
  float* chi = eA1 + 16;          // [64] q0..5 factor after layer-0 pass-1 gates
  float* psi = chi + 64;          // [64] q10..15 factor after layer-0 L gates
  float* PM  = psi + 64;          // [16] q6..9 product
  float* rbuf = PM + 16;          // [16]

  const int b = blockIdx.x, tid = threadIdx.x;
  const int lane = tid & 31, wid = tid >> 5;
  float* st     = g_state + (size_t)b * NSTATE;
  float* mytile = tiles + wid * TILE_F;

  if (tid < 128) {
    float c, s; sincosf(0.5f * w[tid], &s, &c);
    wc[tid] = c; ws[tid] = s; wt[tid] = s / c;
  } else if (tid < 144) {
    int q = tid - 128;
    float c, s; sincosf(0.5f * x[b * 16 + q], &s, &c);
    eA0[q] = (c - s) * 0.7071067811865476f;
    eA1[q] = (c + s) * 0.7071067811865476f;
  }
  if (tid < 16) rbuf[tid] = 0.f;
  __syncthreads();

  // per-layer cos-product: d=0 -> q5..10 only; d=7 -> q0..10; else q0..15
  if (tid < 8) {
    int d = tid; float p = 1.f;
    int qa = (d == 0) ? 5 : 0;
    int qb = (d == 7 || d == 0) ? 10 : 15;
    for (int q = qa; q <= qb; q++) p *= wc[d * 16 + q];
    CS[d] = p;
  }

  // product factors: chi bit5=q0..bit0=q5 ; psi bit5=q10..bit0=q15 ; PM bit3=q6..bit0=q9
  if (tid < 64) {
    float p = 1.f, p2 = 1.f;
#pragma unroll
    for (int k = 0; k < 6; k++) {
      int bit = (tid >> (5 - k)) & 1;
      p  *= bit ? eA1[k]      : eA0[k];
      p2 *= bit ? eA1[10 + k] : eA0[10 + k];
    }
    chi[tid] = p; psi[tid] = p2;
  }
  if (tid < 16) {
    float p = ((tid & 8) ? eA1[6] : eA0[6]) * ((tid & 4) ? eA1[7] : eA0[7])
            * ((tid & 2) ? eA1[8] : eA0[8]) * ((tid & 1) ? eA1[9] : eA0[9]);
    PM[tid] = p;
  }
  __syncthreads();

  // layer-0 exact gates on chi (E(0,1)(2,3)(4,5); O(1,2)(3,4); RY(0..4))
  // and psi (E(10,11)(12,13)(14,15); O(11,12)(13,14); RY(11..15))
  {
    float vc = 0.f, vp = 0.f;
    if (tid < 64) {
      int g = tid;
      if (g & 16) g ^= 8;  if (g & 4)  g ^= 2;
      if (g & 32) g ^= 16; if (g & 8)  g ^= 4; if (g & 2) g ^= 1;
      vc = chi[g]; vp = psi[g];
    }
    __syncthreads();
    if (tid < 64) { chi[tid] = vc; psi[tid] = vp; }
    __syncthreads();
#pragma unroll 1
    for (int k = 0; k < 5; k++) {
      const int mA = 32 >> k, mB = 16 >> k;
      const float cA = wc[k], sA = ws[k], cB = wc[11 + k], sB = ws[11 + k];
      float a1 = 0.f, b1 = 0.f, a2 = 0.f, b2 = 0.f;
      if (tid < 64) { a1 = chi[tid]; b1 = chi[tid ^ mA]; a2 = psi[tid]; b2 = psi[tid ^ mB]; }
      __syncthreads();
      if (tid < 64) {
        chi[tid] = (tid & mA) ? fmaf(cA, a1, sA * b1) : fmaf(cA, a1, -(sA * b1));
        psi[tid] = (tid & mB) ? fmaf(cB, a2, sB * b2) : fmaf(cB, a2, -(sB * b2));
      }
      __syncthreads();
    }
  }

  float acc[10];
#pragma unroll
  for (int q = 0; q < 10; q++) acc[q] = 0.f;

#pragma unroll 1
  for (int d = 0; d < 8; d++) {
    const float* lt = wt + d * 16;

    // ===== Pass 1: q0..5 (idx bits 15..10); coalesced stride-4KB scalar =====
    if (d > 0) {
#pragma unroll 1
      for (int it = 0; it < 4; it++) {
        float* base = st + it * 256 + tid;
        float2 r[32];              // fi: q0=16,q1=8,q2=4,q3=2,q4=1 ; comp=q5
#pragma unroll
        for (int j = 0; j < 32; j++) {
          r[j].x = base[(2 * j) * 1024];
          r[j].y = base[(2 * j + 1) * 1024];
        }
        cnot2<16, 8>(r); cnot2<4, 2>(r); cnotc<1>(r);   // E(0,1)(2,3)(4,5)
        cnot2<8, 4>(r);  cnot2<2, 1>(r);                // O(1,2)(3,4)
        ry2t<16>(r, lt[0]);
        ry2t<8> (r, lt[1]);
        ry2t<4> (r, lt[2]);
        ry2t<2> (r, lt[3]);
        ry2t<1> (r, lt[4]);                             // RY(5) deferred to M
#pragma unroll
        for (int j = 0; j < 32; j++) {
          base[(2 * j) * 1024]     = r[j].x;
          base[(2 * j + 1) * 1024] = r[j].y;
        }
      }
      __syncthreads();
    }

    // ===== Pass 2: per-warp 8KB supertile, idx bits 10..0 ; s = bits 15..11 =====
#pragma unroll 1
    for (int it = 0; it < 4; it++) {
      const int s = it * 8 + wid;
      float2 m2[32];               // fi: q5=16,q6=8,q7=4,q8=2,q9=1 ; comp=q10
      if (d == 0) {
        const float C0 = chi[2 * s], C1 = chi[2 * s + 1];
        const float p0 = psi[lane], p1 = psi[32 + lane];
#pragma unroll
        for (int fj = 0; fj < 32; fj++) {
          float bse = ((fj & 16) ? C1 : C0) * PM[fj & 15];
          m2[fj] = make_float2(bse * p0, bse * p1);
        }
      } else {
        const float4* g4 = (const float4*)(st + s * 2048);
#pragma unroll
        for (int i = 0; i < 16; i++) {
          float4 v = g4[i * 32 + lane];
          *(float4*)(mytile + 136 * i + 4 * lane + 4 * (lane >> 4)) = v;
        }
        __syncwarp();
        if (d < 7) {
          // L phase: row = lane; fi: q10=16,q11=8,q12=4,q13=2,q14=1 ; comp=q15
          float2 r[32];
#pragma unroll
          for (int k = 0; k < 16; k++) {
            float4 v = *(const float4*)(mytile + 68 * lane + 4 * k);
            r[2 * k]     = make_float2(v.x, v.y);
            r[2 * k + 1] = make_float2(v.z, v.w);
          }
          cnot2<16, 8>(r); cnot2<4, 2>(r); cnotc<1>(r); // E(10,11)(12,13)(14,15)
          cnot2<8, 4>(r);  cnot2<2, 1>(r);              // O(11,12)(13,14)
          ry2t<8>(r, lt[11]);
          ry2t<4>(r, lt[12]);
          ry2t<2>(r, lt[13]);
          ry2t<1>(r, lt[14]);
          ryct   (r, lt[15]);                           // RY(10) deferred to M
#pragma unroll
          for (int k = 0; k < 16; k++)
            *(float4*)(mytile + 68 * lane + 4 * k) =
              make_float4(r[2 * k].x, r[2 * k].y, r[2 * k + 1].x, r[2 * k + 1].y);
          __syncwarp();
#pragma unroll
          for (int fj = 0; fj < 32; fj++) {
            m2[fj].x = mytile[68 * fj + lane];
            m2[fj].y = mytile[68 * fj + 32 + lane];
          }
        } else {
          // layer 7: only CNOT(10,11) of the L group affects q0..9 -> fold into addressing
#pragma unroll
          for (int fj = 0; fj < 32; fj++) {
            m2[fj].x = mytile[68 * fj + lane];
            m2[fj].y = mytile[68 * fj + 32 + (lane ^ 16)];
          }
        }
      }
      // M gates (q5..10), tan-form
      cnot2<8, 4>(m2); cnot2<2, 1>(m2);                 // E(6,7)(8,9)
      cnot2<16, 8>(m2); cnot2<4, 2>(m2); cnotc<1>(m2);  // O(5,6)(7,8)(9,10)
      ry2t<16>(m2, lt[5]);
      ry2t<8> (m2, lt[6]);
      ry2t<4> (m2, lt[7]);
      ry2t<2> (m2, lt[8]);
      ry2t<1> (m2, lt[9]);
      ryct    (m2, lt[10]);
      if (d < 7) {
        scale32(m2, CS[d]);                             // fold all cos factors once
        float* o = st + s * 2048 + lane;
#pragma unroll
        for (int fj = 0; fj < 32; fj++) {
          o[(2 * fj) * 32]     = m2[fj].x;
          o[(2 * fj + 1) * 32] = m2[fj].y;
        }
      } else {
        float T = 0.f, m5 = 0.f, m6 = 0.f, m7 = 0.f, m8 = 0.f, m9 = 0.f;
#pragma unroll
        for (int i = 0; i < 32; i++) {
          float p = fmaf(m2[i].x, m2[i].x, m2[i].y * m2[i].y);
          T += p;
          if (i & 16) m5 += p;
          if (i & 8)  m6 += p;
          if (i & 4)  m7 += p;
          if (i & 2)  m8 += p;
          if (i & 1)  m9 += p;
        }
        const float sc2 = CS[7] * CS[7];
        T *= sc2; m5 *= sc2; m6 *= sc2; m7 *= sc2; m8 *= sc2; m9 *= sc2;
#pragma unroll
        for (int q = 0; q < 5; q++)
          acc[q] += ((s >> (4 - q)) & 1) ? -T : T;
        acc[5] += T - 2.f * m5;
        acc[6] += T - 2.f * m6;
        acc[7] += T - 2.f * m7;
        acc[8] += T - 2.f * m8;
        acc[9] += T - 2.f * m9;
      }
    }
    __syncthreads();
  }

#pragma unroll
  for (int q = 0; q < 10; q++)
#pragma unroll
    for (int off = 16; off > 0; off >>= 1)
      acc[q] += __shfl_xor_sync(0xffffffffu, acc[q], off);
  if (lane == 0)
#pragma unroll
    for (int q = 0; q < 10; q++) atomicAdd(&rbuf[q], acc[q]);
  __syncthreads();
  if (tid < 10) out[b * 10 + tid] = rbuf[tid];
}

extern "C" void kernel_launch(void* const* d_in, const int* in_sizes, int n_in,
                              void* d_out, int out_size) {
  const float* x = (const float*)d_in[0];
  const float* w = (const float*)d_in[1];
  float* out = (float*)d_out;
  int B = in_sizes[0] / 16;
  if (B > BMAX) B = BMAX;
  cudaFuncSetAttribute(vqc_kernel, cudaFuncAttributeMaxDynamicSharedMemorySize,
                       SMEM_BYTES);
  vqc_kernel<<<B, 256, SMEM_BYTES>>>(x, w, out);
}

// round 11
// speedup vs baseline: 1.3833x; 1.3833x over previous
#include <cuda_runtime.h>
#include <cuda_fp16.h>

#define NSTATE 65536
#define BMAX   1024

// per-sample state scratch in fp16; working set 296 CTAs * 128KB = 38MB -> deep L2 residency
__device__ __align__(16) __half g_state[(size_t)BMAX * NSTATE];

__device__ __forceinline__ unsigned long long pk2(float a, float b) {
  unsigned long long r;
  asm("mov.b64 %0, {%1, %2};" : "=l"(r) : "f"(a), "f"(b));
  return r;
}

// tan-form RY (packed f32x2): lo' = lo - t*hi ; hi' = hi + t*lo
template<int S2>
__device__ __forceinline__ void ry2t(float2* r, float t) {
  const unsigned long long t2 = pk2(t, t), nt2 = pk2(-t, -t);
#pragma unroll
  for (int base = 0; base < 32; base += 2 * S2)
#pragma unroll
    for (int k = 0; k < S2; k++) {
      unsigned long long lo = *(unsigned long long*)&r[base + k];
      unsigned long long hi = *(unsigned long long*)&r[base + k + S2];
      unsigned long long nlo, nhi;
      asm("fma.rn.f32x2 %0, %1, %2, %3;" : "=l"(nlo) : "l"(nt2), "l"(hi), "l"(lo));
      asm("fma.rn.f32x2 %0, %1, %2, %3;" : "=l"(nhi) : "l"(t2),  "l"(lo), "l"(hi));
      *(unsigned long long*)&r[base + k]      = nlo;
      *(unsigned long long*)&r[base + k + S2] = nhi;
    }
}

__device__ __forceinline__ void ryct(float2* r, float t) {
#pragma unroll
  for (int i = 0; i < 32; i++) {
    float x = r[i].x, y = r[i].y;
    r[i].x = fmaf(-t, y, x);
    r[i].y = fmaf( t, x, y);
  }
}

__device__ __forceinline__ void scale32(float2* r, float c) {
  const unsigned long long c2 = pk2(c, c);
#pragma unroll
  for (int i = 0; i < 32; i++) {
    unsigned long long v = *(unsigned long long*)&r[i], o;
    asm("mul.rn.f32x2 %0, %1, %2;" : "=l"(o) : "l"(c2), "l"(v));
    *(unsigned long long*)&r[i] = o;
  }
}

template<int C2, int T2>
__device__ __forceinline__ void cnot2(float2* r) {
#pragma unroll
  for (int i = 0; i < 32; i++)
    if ((i & C2) && !(i & T2)) { float2 t = r[i]; r[i] = r[i | T2]; r[i | T2] = t; }
}
template<int C2>
__device__ __forceinline__ void cnotc(float2* r) {
#pragma unroll
  for (int i = 0; i < 32; i++)
    if (i & C2) { float t = r[i].x; r[i].x = r[i].y; r[i].y = t; }
}

// per-warp fp16 tile: 32 rows * 72 halves (8-half pad -> conflict-free)
#define TILE_H    (32 * 72)
#define TILE_B    (TILE_H * 2)        // 4608 bytes
#define TILES_B   (8 * TILE_B)        // 36864
#define TABLE_F   (128 + 128 + 128 + 16 + 16 + 16 + 64 + 64 + 16 + 16)
#define SMEM_BYTES (TILES_B + TABLE_F * 4)

__global__ void __launch_bounds__(256, 2)
vqc_kernel(const float* __restrict__ x, const float* __restrict__ w,
           float* __restrict__ out)
{
  extern __shared__ char smb[];
  __half* tiles_h = (__half*)smb;
  float* wc  = (float*)(smb + TILES_B);   // [8][16] cos(w/2)
  float* ws  = wc + 128;                  // [8][16] sin(w/2)
  float* wt  = ws + 128;                  // [8][16] tan(w/2)
  float* CS  = wt + 128;                  // [8] per-layer cos-product scale
  float* eA0 = CS + 16;
  float* eA1 = eA0 + 16;
  float* chi = eA1 + 16;                  // [64] q0..5 factor after layer-0 pass-1 gates
  float* psi = chi + 64;                  // [64] q10..15 factor after layer-0 L gates
  float* PM  = psi + 64;                  // [16] q6..9 product
  float* rbuf = PM + 16;                  // [16]

  const int b = blockIdx.x, tid = threadIdx.x;
  const int lane = tid & 31, wid = tid >> 5;
  __half* st      = g_state + (size_t)b * NSTATE;
  __half* mytile  = tiles_h + wid * TILE_H;

  if (tid < 128) {
    float c, s; sincosf(0.5f * w[tid], &s, &c);
    wc[tid] = c; ws[tid] = s; wt[tid] = s / c;
  } else if (tid < 144) {
    int q = tid - 128;
    float c, s; sincosf(0.5f * x[b * 16 + q], &s, &c);
    eA0[q] = (c - s) * 0.7071067811865476f;
    eA1[q] = (c + s) * 0.7071067811865476f;
  }
  if (tid < 16) rbuf[tid] = 0.f;
  __syncthreads();

  // per-layer cos-product: d=0 -> q5..10 only; d=7 -> q0..10; else q0..15
  if (tid < 8) {
    int d = tid; float p = 1.f;
    int qa = (d == 0) ? 5 : 0;
    int qb = (d == 7 || d == 0) ? 10 : 15;
    for (int q = qa; q <= qb; q++) p *= wc[d * 16 + q];
    CS[d] = p;
  }

  // product factors: chi bit5=q0..bit0=q5 ; psi bit5=q10..bit0=q15 ; PM bit3=q6..bit0=q9
  if (tid < 64) {
    float p = 1.f, p2 = 1.f;
#pragma unroll
    for (int k = 0; k < 6; k++) {
      int bit = (tid >> (5 - k)) & 1;
      p  *= bit ? eA1[k]      : eA0[k];
      p2 *= bit ? eA1[10 + k] : eA0[10 + k];
    }
    chi[tid] = p; psi[tid] = p2;
  }
  if (tid < 16) {
    float p = ((tid & 8) ? eA1[6] : eA0[6]) * ((tid & 4) ? eA1[7] : eA0[7])
            * ((tid & 2) ? eA1[8] : eA0[8]) * ((tid & 1) ? eA1[9] : eA0[9]);
    PM[tid] = p;
  }
  __syncthreads();

  // layer-0 exact gates on chi and psi (same masks)
  {
    float vc = 0.f, vp = 0.f;
    if (tid < 64) {
      int g = tid;
      if (g & 16) g ^= 8;  if (g & 4)  g ^= 2;
      if (g & 32) g ^= 16; if (g & 8)  g ^= 4; if (g & 2) g ^= 1;
      vc = chi[g]; vp = psi[g];
    }
    __syncthreads();
    if (tid < 64) { chi[tid] = vc; psi[tid] = vp; }
    __syncthreads();
#pragma unroll 1
    for (int k = 0; k < 5; k++) {
      const int mA = 32 >> k, mB = 16 >> k;
      const float cA = wc[k], sA = ws[k], cB = wc[11 + k], sB = ws[11 + k];
      float a1 = 0.f, b1 = 0.f, a2 = 0.f, b2 = 0.f;
      if (tid < 64) { a1 = chi[tid]; b1 = chi[tid ^ mA]; a2 = psi[tid]; b2 = psi[tid ^ mB]; }
      __syncthreads();
      if (tid < 64) {
        chi[tid] = (tid & mA) ? fmaf(cA, a1, sA * b1) : fmaf(cA, a1, -(sA * b1));
        psi[tid] = (tid & mB) ? fmaf(cB, a2, sB * b2) : fmaf(cB, a2, -(sB * b2));
      }
      __syncthreads();
    }
  }

  float acc[10];
#pragma unroll
  for (int q = 0; q < 10; q++) acc[q] = 0.f;

#pragma unroll 1
  for (int d = 0; d < 8; d++) {
    const float* lt = wt + d * 16;

    // ===== Pass 1: q0..5 (idx bits 15..10); coalesced 16-bit, stride 1024 elems =====
    if (d > 0) {
#pragma unroll 1
      for (int it = 0; it < 4; it++) {
        __half* base = st + it * 256 + tid;
        float2 r[32];              // fi: q0=16,q1=8,q2=4,q3=2,q4=1 ; comp=q5
#pragma unroll
        for (int j = 0; j < 32; j++) {
          r[j].x = __half2float(base[(2 * j) * 1024]);
          r[j].y = __half2float(base[(2 * j + 1) * 1024]);
        }
        cnot2<16, 8>(r); cnot2<4, 2>(r); cnotc<1>(r);   // E(0,1)(2,3)(4,5)
        cnot2<8, 4>(r);  cnot2<2, 1>(r);                // O(1,2)(3,4)
        ry2t<16>(r, lt[0]);
        ry2t<8> (r, lt[1]);
        ry2t<4> (r, lt[2]);
        ry2t<2> (r, lt[3]);
        ry2t<1> (r, lt[4]);                             // RY(5) deferred to M
#pragma unroll
        for (int j = 0; j < 32; j++) {
          base[(2 * j) * 1024]     = __float2half_rn(r[j].x);
          base[(2 * j + 1) * 1024] = __float2half_rn(r[j].y);
        }
      }
      __syncthreads();
    }

    // ===== Pass 2: per-warp 4KB fp16 supertile, idx bits 10..0 =====
#pragma unroll 1
    for (int it = 0; it < 4; it++) {
      const int s = it * 8 + wid;
      float2 m2[32];               // fi: q5=16,q6=8,q7=4,q8=2,q9=1 ; comp=q10
      if (d == 0) {
        const float C0 = chi[2 * s], C1 = chi[2 * s + 1];
        const float p0 = psi[lane], p1 = psi[32 + lane];
#pragma unroll
        for (int fj = 0; fj < 32; fj++) {
          float bse = ((fj & 16) ? C1 : C0) * PM[fj & 15];
          m2[fj] = make_float2(bse * p0, bse * p1);
        }
      } else {
        // ingest: 2048 halves = 256 uint4 chunks; 8 x LDG.128 per thread
        const uint4* g4 = (const uint4*)(st + s * 2048);
#pragma unroll
        for (int i = 0; i < 8; i++) {
          uint4 v = g4[i * 32 + lane];
          int c = i * 32 + lane;                 // 8-half chunk index, 0..255
          *(uint4*)(mytile + (c >> 3) * 72 + (c & 7) * 8) = v;
        }
        __syncwarp();
        if (d < 7) {
          // L phase: row = lane (q5..9); fi: q10=16..q14=1 ; comp=q15
          float2 r[32];
          const uint4* rowp = (const uint4*)(mytile + lane * 72);
#pragma unroll
          for (int k = 0; k < 8; k++) {
            uint4 v = rowp[k];
            const __half2* h = (const __half2*)&v;
            r[4 * k + 0] = __half22float2(h[0]);
            r[4 * k + 1] = __half22float2(h[1]);
            r[4 * k + 2] = __half22float2(h[2]);
            r[4 * k + 3] = __half22float2(h[3]);
          }
          cnot2<16, 8>(r); cnot2<4, 2>(r); cnotc<1>(r); // E(10,11)(12,13)(14,15)
          cnot2<8, 4>(r);  cnot2<2, 1>(r);              // O(11,12)(13,14)
          ry2t<8>(r, lt[11]);
          ry2t<4>(r, lt[12]);
          ry2t<2>(r, lt[13]);
          ry2t<1>(r, lt[14]);
          ryct   (r, lt[15]);                           // RY(10) deferred to M
          // write-back packed as (v=c, v=c+32) half2 pairs -> conflict-free M reads
#pragma unroll
          for (int c = 0; c < 32; c++) {
            float a = (c & 1) ? r[c >> 1].y        : r[c >> 1].x;
            float g = (c & 1) ? r[16 + (c >> 1)].y : r[16 + (c >> 1)].x;
            *(__half2*)(mytile + lane * 72 + 2 * c) = __floats2half2_rn(a, g);
          }
          __syncwarp();
#pragma unroll
          for (int fj = 0; fj < 32; fj++)
            m2[fj] = __half22float2(*(const __half2*)(mytile + fj * 72 + 2 * lane));
        } else {
          // layer 7: only CNOT(10,11) survives -> fold into addressing (natural row order)
#pragma unroll
          for (int fj = 0; fj < 32; fj++) {
            m2[fj].x = __half2float(mytile[fj * 72 + lane]);
            m2[fj].y = __half2float(mytile[fj * 72 + 32 + (lane ^ 16)]);
          }
        }
      }
      // M gates (q5..10), tan-form
      cnot2<8, 4>(m2); cnot2<2, 1>(m2);                 // E(6,7)(8,9)
      cnot2<16, 8>(m2); cnot2<4, 2>(m2); cnotc<1>(m2);  // O(5,6)(7,8)(9,10)
      ry2t<16>(m2, lt[5]);
      ry2t<8> (m2, lt[6]);
      ry2t<4> (m2, lt[7]);
      ry2t<2> (m2, lt[8]);
      ry2t<1> (m2, lt[9]);
      ryct    (m2, lt[10]);
      if (d < 7) {
        scale32(m2, CS[d]);
        __half* o = st + s * 2048 + lane;
#pragma unroll
        for (int fj = 0; fj < 32; fj++) {
          o[fj * 64]      = __float2half_rn(m2[fj].x);
          o[fj * 64 + 32] = __float2half_rn(m2[fj].y);
        }
      } else {
        float T = 0.f, m5 = 0.f, m6 = 0.f, m7 = 0.f, m8 = 0.f, m9 = 0.f;
#pragma unroll
        for (int i = 0; i < 32; i++) {
          float p = fmaf(m2[i].x, m2[i].x, m2[i].y * m2[i].y);
          T += p;
          if (i & 16) m5 += p;
          if (i & 8)  m6 += p;
          if (i & 4)  m7 += p;
          if (i & 2)  m8 += p;
          if (i & 1)  m9 += p;
        }
        const float sc2 = CS[7] * CS[7];
        T *= sc2; m5 *= sc2; m6 *= sc2; m7 *= sc2; m8 *= sc2; m9 *= sc2;
#pragma unroll
        for (int q = 0; q < 5; q++)
          acc[q] += ((s >> (4 - q)) & 1) ? -T : T;
        acc[5] += T - 2.f * m5;
        acc[6] += T - 2.f * m6;
        acc[7] += T - 2.f * m7;
        acc[8] += T - 2.f * m8;
        acc[9] += T - 2.f * m9;
      }
    }
    __syncthreads();
  }

#pragma unroll
  for (int q = 0; q < 10; q++)
#pragma unroll
    for (int off = 16; off > 0; off >>= 1)
      acc[q] += __shfl_xor_sync(0xffffffffu, acc[q], off);
  if (lane == 0)
#pragma unroll
    for (int q = 0; q < 10; q++) atomicAdd(&rbuf[q], acc[q]);
  __syncthreads();
  if (tid < 10) out[b * 10 + tid] = rbuf[tid];
}

extern "C" void kernel_launch(void* const* d_in, const int* in_sizes, int n_in,
                              void* d_out, int out_size) {
  const float* x = (const float*)d_in[0];
  const float* w = (const float*)d_in[1];
  float* out = (float*)d_out;
  int B = in_sizes[0] / 16;
  if (B > BMAX) B = BMAX;
  cudaFuncSetAttribute(vqc_kernel, cudaFuncAttributeMaxDynamicSharedMemorySize,
                       SMEM_BYTES);
  vqc_kernel<<<B, 256, SMEM_BYTES>>>(x, w, out);
}

// round 12
// speedup vs baseline: 1.4553x; 1.0521x over previous
#include <cuda_runtime.h>
#include <cuda_fp16.h>

#define BMAX   1024

#define ROWP 76                        // halves per padded row (64 data + 12 pad)
#define TILE_HALVES (32 * ROWP)        // 2432
#define STATE_HALVES (32 * TILE_HALVES)
#define STATE_BYTES (STATE_HALVES * 2) // 155648
#define TABLE_F (128 + 128 + 128 + 16 + 16 + 16 + 64 + 64 + 16 + 16)
#define SMEM_BYTES (STATE_BYTES + TABLE_F * 4)

__device__ __forceinline__ unsigned long long pk2(float a, float b) {
  unsigned long long r;
  asm("mov.b64 %0, {%1, %2};" : "=l"(r) : "f"(a), "f"(b));
  return r;
}

// tan-form RY (packed f32x2): lo' = lo - t*hi ; hi' = hi + t*lo
template<int S2>
__device__ __forceinline__ void ry2t(float2* r, float t) {
  const unsigned long long t2 = pk2(t, t), nt2 = pk2(-t, -t);
#pragma unroll
  for (int base = 0; base < 32; base += 2 * S2)
#pragma unroll
    for (int k = 0; k < S2; k++) {
      unsigned long long lo = *(unsigned long long*)&r[base + k];
      unsigned long long hi = *(unsigned long long*)&r[base + k + S2];
      unsigned long long nlo, nhi;
      asm("fma.rn.f32x2 %0, %1, %2, %3;" : "=l"(nlo) : "l"(nt2), "l"(hi), "l"(lo));
      asm("fma.rn.f32x2 %0, %1, %2, %3;" : "=l"(nhi) : "l"(t2),  "l"(lo), "l"(hi));
      *(unsigned long long*)&r[base + k]      = nlo;
      *(unsigned long long*)&r[base + k + S2] = nhi;
    }
}

__device__ __forceinline__ void ryct(float2* r, float t) {
#pragma unroll
  for (int i = 0; i < 32; i++) {
    float x = r[i].x, y = r[i].y;
    r[i].x = fmaf(-t, y, x);
    r[i].y = fmaf( t, x, y);
  }
}

__device__ __forceinline__ void scale32(float2* r, float c) {
  const unsigned long long c2 = pk2(c, c);
#pragma unroll
  for (int i = 0; i < 32; i++) {
    unsigned long long v = *(unsigned long long*)&r[i], o;
    asm("mul.rn.f32x2 %0, %1, %2;" : "=l"(o) : "l"(c2), "l"(v));
    *(unsigned long long*)&r[i] = o;
  }
}

template<int C2, int T2>
__device__ __forceinline__ void cnot2(float2* r) {
#pragma unroll
  for (int i = 0; i < 32; i++)
    if ((i & C2) && !(i & T2)) { float2 t = r[i]; r[i] = r[i | T2]; r[i | T2] = t; }
}
template<int C2>
__device__ __forceinline__ void cnotc(float2* r) {
#pragma unroll
  for (int i = 0; i < 32; i++)
    if (i & C2) { float t = r[i].x; r[i].x = r[i].y; r[i].y = t; }
}

__global__ void __launch_bounds__(256, 1)
vqc_kernel(const float* __restrict__ x, const float* __restrict__ w,
           float* __restrict__ out)
{
  extern __shared__ char smb[];
  __half* st = (__half*)smb;              // whole 16-qubit state, 32 padded tiles
  float* wc  = (float*)(smb + STATE_BYTES);   // [8][16] cos(w/2)
  float* ws  = wc + 128;                  // [8][16] sin(w/2)
  float* wt  = ws + 128;                  // [8][16] tan(w/2)
  float* CS  = wt + 128;                  // [8] per-layer cos-product scale
  float* eA0 = CS + 16;
  float* eA1 = eA0 + 16;
  float* chi = eA1 + 16;                  // [64] q0..5 factor after layer-0 pass-1 gates
  float* psi = chi + 64;                  // [64] q10..15 factor after layer-0 L gates
  float* PM  = psi + 64;                  // [16] q6..9 product
  float* rbuf = PM + 16;                  // [16]

  const int b = blockIdx.x, tid = threadIdx.x;
  const int lane = tid & 31, wid = tid >> 5;

  if (tid < 128) {
    float c, s; sincosf(0.5f * w[tid], &s, &c);
    wc[tid] = c; ws[tid] = s; wt[tid] = s / c;
  } else if (tid < 144) {
    int q = tid - 128;
    float c, s; sincosf(0.5f * x[b * 16 + q], &s, &c);
    eA0[q] = (c - s) * 0.7071067811865476f;
    eA1[q] = (c + s) * 0.7071067811865476f;
  }
  if (tid < 16) rbuf[tid] = 0.f;
  __syncthreads();

  // per-layer cos-product: d=0 -> q5..10 only; d=7 -> q0..10; else q0..15
  if (tid < 8) {
    int d = tid; float p = 1.f;
    int qa = (d == 0) ? 5 : 0;
    int qb = (d == 7 || d == 0) ? 10 : 15;
    for (int q = qa; q <= qb; q++) p *= wc[d * 16 + q];
    CS[d] = p;
  }

  // product factors: chi bit5=q0..bit0=q5 ; psi bit5=q10..bit0=q15 ; PM bit3=q6..bit0=q9
  if (tid < 64) {
    float p = 1.f, p2 = 1.f;
#pragma unroll
    for (int k = 0; k < 6; k++) {
      int bit = (tid >> (5 - k)) & 1;
      p  *= bit ? eA1[k]      : eA0[k];
      p2 *= bit ? eA1[10 + k] : eA0[10 + k];
    }
    chi[tid] = p; psi[tid] = p2;
  }
  if (tid < 16) {
    float p = ((tid & 8) ? eA1[6] : eA0[6]) * ((tid & 4) ? eA1[7] : eA0[7])
            * ((tid & 2) ? eA1[8] : eA0[8]) * ((tid & 1) ? eA1[9] : eA0[9]);
    PM[tid] = p;
  }
  __syncthreads();

  // layer-0 exact gates on chi and psi (same masks)
  {
    float vc = 0.f, vp = 0.f;
    if (tid < 64) {
      int g = tid;
      if (g & 16) g ^= 8;  if (g & 4)  g ^= 2;
      if (g & 32) g ^= 16; if (g & 8)  g ^= 4; if (g & 2) g ^= 1;
      vc = chi[g]; vp = psi[g];
    }
    __syncthreads();
    if (tid < 64) { chi[tid] = vc; psi[tid] = vp; }
    __syncthreads();
#pragma unroll 1
    for (int k = 0; k < 5; k++) {
      const int mA = 32 >> k, mB = 16 >> k;
      const float cA = wc[k], sA = ws[k], cB = wc[11 + k], sB = ws[11 + k];
      float a1 = 0.f, b1 = 0.f, a2 = 0.f, b2 = 0.f;
      if (tid < 64) { a1 = chi[tid]; b1 = chi[tid ^ mA]; a2 = psi[tid]; b2 = psi[tid ^ mB]; }
      __syncthreads();
      if (tid < 64) {
        chi[tid] = (tid & mA) ? fmaf(cA, a1, sA * b1) : fmaf(cA, a1, -(sA * b1));
        psi[tid] = (tid & mB) ? fmaf(cB, a2, sB * b2) : fmaf(cB, a2, -(sB * b2));
      }
      __syncthreads();
    }
  }

  float acc[10];
#pragma unroll
  for (int q = 0; q < 10; q++) acc[q] = 0.f;

  // state layout: idx bits 15..11 = tile t (q0..4); bit10 = q5 (tile row bit4);
  // within tile: row = bits10..6 (q5, q6..9), col = bits5..0 (q10, q11..15),
  // phys = t*2432 + row*76 + col
#pragma unroll 1
  for (int d = 0; d < 8; d++) {
    const float* lt = wt + d * 16;

    // ===== Pass 1: window over q0..5; fixed (q6..15) per thread; all in smem =====
    if (d > 0) {
#pragma unroll 1
      for (int it = 0; it < 4; it++) {
        const int low10 = it * 256 + tid;
        const int rfix = low10 >> 6;          // q6..9 -> row bits 3..0
        const int cfix = low10 & 63;          // q10..15 -> col
        float2 r[32];              // fi: q0=16,q1=8,q2=4,q3=2,q4=1 ; comp=q5
#pragma unroll
        for (int fi = 0; fi < 32; fi++) {
          r[fi].x = __half2float(st[fi * TILE_HALVES + rfix * ROWP + cfix]);
          r[fi].y = __half2float(st[fi * TILE_HALVES + (rfix + 16) * ROWP + cfix]);
        }
        cnot2<16, 8>(r); cnot2<4, 2>(r); cnotc<1>(r);   // E(0,1)(2,3)(4,5)
        cnot2<8, 4>(r);  cnot2<2, 1>(r);                // O(1,2)(3,4)
        ry2t<16>(r, lt[0]);
        ry2t<8> (r, lt[1]);
        ry2t<4> (r, lt[2]);
        ry2t<2> (r, lt[3]);
        ry2t<1> (r, lt[4]);                             // RY(5) deferred to M
#pragma unroll
        for (int fi = 0; fi < 32; fi++) {
          st[fi * TILE_HALVES + rfix * ROWP + cfix]        = __float2half_rn(r[fi].x);
          st[fi * TILE_HALVES + (rfix + 16) * ROWP + cfix] = __float2half_rn(r[fi].y);
        }
      }
      __syncthreads();
    }

    // ===== Pass 2: per-warp tiles (L phase on q10..15, M phase on q5..10) =====
#pragma unroll 1
    for (int it = 0; it < 4; it++) {
      const int s = it * 8 + wid;
      __half* tl = st + s * TILE_HALVES;
      float2 m2[32];               // fi: q5=16,q6=8,q7=4,q8=2,q9=1 ; comp=q10
      if (d == 0) {
        const float C0 = chi[2 * s], C1 = chi[2 * s + 1];
        const float p0 = psi[lane], p1 = psi[32 + lane];
#pragma unroll
        for (int fj = 0; fj < 32; fj++) {
          float bse = ((fj & 16) ? C1 : C0) * PM[fj & 15];
          m2[fj] = make_float2(bse * p0, bse * p1);
        }
      } else {
        if (d < 7) {
          // L phase: thread = row (one q5..9 value); window = 64 cols (q10..15)
          // fi: q10=16,q11=8,q12=4,q13=2,q14=1 ; comp=q15 -> consecutive halves
          float2 r[32];
          const uint2* rowp = (const uint2*)(tl + lane * ROWP);
#pragma unroll
          for (int k = 0; k < 16; k++) {
            uint2 v = rowp[k];
            const __half2* h = (const __half2*)&v;
            r[2 * k]     = __half22float2(h[0]);
            r[2 * k + 1] = __half22float2(h[1]);
          }
          cnot2<16, 8>(r); cnot2<4, 2>(r); cnotc<1>(r); // E(10,11)(12,13)(14,15)
          cnot2<8, 4>(r);  cnot2<2, 1>(r);              // O(11,12)(13,14)
          ry2t<8>(r, lt[11]);
          ry2t<4>(r, lt[12]);
          ry2t<2>(r, lt[13]);
          ry2t<1>(r, lt[14]);
          ryct   (r, lt[15]);                           // RY(10) deferred to M
          uint2* roww = (uint2*)(tl + lane * ROWP);
#pragma unroll
          for (int k = 0; k < 16; k++) {
            uint2 v;
            __half2* h = (__half2*)&v;
            h[0] = __floats2half2_rn(r[2 * k].x,     r[2 * k].y);
            h[1] = __floats2half2_rn(r[2 * k + 1].x, r[2 * k + 1].y);
            roww[k] = v;
          }
          __syncwarp();
          // M read: column lane (q11..15 fixed), rows = fj, comp = q10 (col +-32)
#pragma unroll
          for (int fj = 0; fj < 32; fj++) {
            m2[fj].x = __half2float(tl[fj * ROWP + lane]);
            m2[fj].y = __half2float(tl[fj * ROWP + 32 + lane]);
          }
        } else {
          // layer 7: L group reduces to CNOT(10,11) -> fold into M addressing
#pragma unroll
          for (int fj = 0; fj < 32; fj++) {
            m2[fj].x = __half2float(tl[fj * ROWP + lane]);
            m2[fj].y = __half2float(tl[fj * ROWP + 32 + (lane ^ 16)]);
          }
        }
      }
      // M gates (q5..10), tan-form
      cnot2<8, 4>(m2); cnot2<2, 1>(m2);                 // E(6,7)(8,9)
      cnot2<16, 8>(m2); cnot2<4, 2>(m2); cnotc<1>(m2);  // O(5,6)(7,8)(9,10)
      ry2t<16>(m2, lt[5]);
      ry2t<8> (m2, lt[6]);
      ry2t<4> (m2, lt[7]);
      ry2t<2> (m2, lt[8]);
      ry2t<1> (m2, lt[9]);
      ryct    (m2, lt[10]);
      if (d < 7) {
        scale32(m2, CS[d]);
#pragma unroll
        for (int fj = 0; fj < 32; fj++) {
          tl[fj * ROWP + lane]      = __float2half_rn(m2[fj].x);
          tl[fj * ROWP + 32 + lane] = __float2half_rn(m2[fj].y);
        }
      } else {
        float T = 0.f, m5 = 0.f, m6 = 0.f, m7 = 0.f, m8 = 0.f, m9 = 0.f;
#pragma unroll
        for (int i = 0; i < 32; i++) {
          float p = fmaf(m2[i].x, m2[i].x, m2[i].y * m2[i].y);
          T += p;
          if (i & 16) m5 += p;
          if (i & 8)  m6 += p;
          if (i & 4)  m7 += p;
          if (i & 2)  m8 += p;
          if (i & 1)  m9 += p;
        }
        const float sc2 = CS[7] * CS[7];
        T *= sc2; m5 *= sc2; m6 *= sc2; m7 *= sc2; m8 *= sc2; m9 *= sc2;
#pragma unroll
        for (int q = 0; q < 5; q++)
          acc[q] += ((s >> (4 - q)) & 1) ? -T : T;
        acc[5] += T - 2.f * m5;
        acc[6] += T - 2.f * m6;
        acc[7] += T - 2.f * m7;
        acc[8] += T - 2.f * m8;
        acc[9] += T - 2.f * m9;
      }
    }
    __syncthreads();
  }

#pragma unroll
  for (int q = 0; q < 10; q++)
#pragma unroll
    for (int off = 16; off > 0; off >>= 1)
      acc[q] += __shfl_xor_sync(0xffffffffu, acc[q], off);
  if (lane == 0)
#pragma unroll
    for (int q = 0; q < 10; q++) atomicAdd(&rbuf[q], acc[q]);
  __syncthreads();
  if (tid < 10) out[b * 10 + tid] = rbuf[tid];
}

extern "C" void kernel_launch(void* const* d_in, const int* in_sizes, int n_in,
                              void* d_out, int out_size) {
  const float* x = (const float*)d_in[0];
  const float* w = (const float*)d_in[1];
  float* out = (float*)d_out;
  int B = in_sizes[0] / 16;
  if (B > BMAX) B = BMAX;
  cudaFuncSetAttribute(vqc_kernel, cudaFuncAttributeMaxDynamicSharedMemorySize,
                       SMEM_BYTES);
  vqc_kernel<<<B, 256, SMEM_BYTES>>>(x, w, out);
}

// round 13
// speedup vs baseline: 1.5167x; 1.0422x over previous
#include <cuda_runtime.h>
#include <cuda_fp16.h>

#define BMAX   1024
#define NTHR   512

#define ROWP 76                        // halves per padded row (64 data + 12 pad)
#define TILE_HALVES (32 * ROWP)        // 2432
#define STATE_HALVES (32 * TILE_HALVES)
#define STATE_BYTES (STATE_HALVES * 2) // 155648
#define TABLE_F (128 + 128 + 128 + 16 + 16 + 16 + 64 + 64 + 16 + 16)
#define SMEM_BYTES (STATE_BYTES + TABLE_F * 4)

__device__ __forceinline__ unsigned long long pk2(float a, float b) {
  unsigned long long r;
  asm("mov.b64 %0, {%1, %2};" : "=l"(r) : "f"(a), "f"(b));
  return r;
}

// tan-form RY (packed f32x2): lo' = lo - t*hi ; hi' = hi + t*lo
template<int S2>
__device__ __forceinline__ void ry2t(float2* r, float t) {
  const unsigned long long t2 = pk2(t, t), nt2 = pk2(-t, -t);
#pragma unroll
  for (int base = 0; base < 32; base += 2 * S2)
#pragma unroll
    for (int k = 0; k < S2; k++) {
      unsigned long long lo = *(unsigned long long*)&r[base + k];
      unsigned long long hi = *(unsigned long long*)&r[base + k + S2];
      unsigned long long nlo, nhi;
      asm("fma.rn.f32x2 %0, %1, %2, %3;" : "=l"(nlo) : "l"(nt2), "l"(hi), "l"(lo));
      asm("fma.rn.f32x2 %0, %1, %2, %3;" : "=l"(nhi) : "l"(t2),  "l"(lo), "l"(hi));
      *(unsigned long long*)&r[base + k]      = nlo;
      *(unsigned long long*)&r[base + k + S2] = nhi;
    }
}

__device__ __forceinline__ void ryct(float2* r, float t) {
#pragma unroll
  for (int i = 0; i < 32; i++) {
    float x = r[i].x, y = r[i].y;
    r[i].x = fmaf(-t, y, x);
    r[i].y = fmaf( t, x, y);
  }
}

__device__ __forceinline__ void scale32(float2* r, float c) {
  const unsigned long long c2 = pk2(c, c);
#pragma unroll
  for (int i = 0; i < 32; i++) {
    unsigned long long v = *(unsigned long long*)&r[i], o;
    asm("mul.rn.f32x2 %0, %1, %2;" : "=l"(o) : "l"(c2), "l"(v));
    *(unsigned long long*)&r[i] = o;
  }
}

template<int C2, int T2>
__device__ __forceinline__ void cnot2(float2* r) {
#pragma unroll
  for (int i = 0; i < 32; i++)
    if ((i & C2) && !(i & T2)) { float2 t = r[i]; r[i] = r[i | T2]; r[i | T2] = t; }
}
template<int C2>
__device__ __forceinline__ void cnotc(float2* r) {
#pragma unroll
  for (int i = 0; i < 32; i++)
    if (i & C2) { float t = r[i].x; r[i].x = r[i].y; r[i].y = t; }
}

__global__ void __launch_bounds__(NTHR, 1)
vqc_kernel(const float* __restrict__ x, const float* __restrict__ w,
           float* __restrict__ out)
{
  extern __shared__ char smb[];
  __half* st = (__half*)smb;              // whole 16-qubit state, 32 padded tiles
  float* wc  = (float*)(smb + STATE_BYTES);   // [8][16] cos(w/2)
  float* ws  = wc + 128;                  // [8][16] sin(w/2)
  float* wt  = ws + 128;                  // [8][16] tan(w/2)
  float* CS  = wt + 128;                  // [8] per-layer cos-product scale
  float* eA0 = CS + 16;
  float* eA1 = eA0 + 16;
  float* chi = eA1 + 16;                  // [64] q0..5 factor after layer-0 pass-1 gates
  float* psi = chi + 64;                  // [64] q10..15 factor after layer-0 L gates
  float* PM  = psi + 64;                  // [16] q6..9 product
  float* rbuf = PM + 16;                  // [16]

  const int b = blockIdx.x, tid = threadIdx.x;
  const int lane = tid & 31, wid = tid >> 5;

  if (tid < 128) {
    float c, s; sincosf(0.5f * w[tid], &s, &c);
    wc[tid] = c; ws[tid] = s; wt[tid] = s / c;
  } else if (tid < 144) {
    int q = tid - 128;
    float c, s; sincosf(0.5f * x[b * 16 + q], &s, &c);
    eA0[q] = (c - s) * 0.7071067811865476f;
    eA1[q] = (c + s) * 0.7071067811865476f;
  }
  if (tid < 16) rbuf[tid] = 0.f;
  __syncthreads();

  // per-layer cos-product: d=0 -> q5..10 only; d=7 -> q0..10; else q0..15
  if (tid < 8) {
    int d = tid; float p = 1.f;
    int qa = (d == 0) ? 5 : 0;
    int qb = (d == 7 || d == 0) ? 10 : 15;
    for (int q = qa; q <= qb; q++) p *= wc[d * 16 + q];
    CS[d] = p;
  }

  // product factors: chi bit5=q0..bit0=q5 ; psi bit5=q10..bit0=q15 ; PM bit3=q6..bit0=q9
  if (tid < 64) {
    float p = 1.f, p2 = 1.f;
#pragma unroll
    for (int k = 0; k < 6; k++) {
      int bit = (tid >> (5 - k)) & 1;
      p  *= bit ? eA1[k]      : eA0[k];
      p2 *= bit ? eA1[10 + k] : eA0[10 + k];
    }
    chi[tid] = p; psi[tid] = p2;
  }
  if (tid < 16) {
    float p = ((tid & 8) ? eA1[6] : eA0[6]) * ((tid & 4) ? eA1[7] : eA0[7])
            * ((tid & 2) ? eA1[8] : eA0[8]) * ((tid & 1) ? eA1[9] : eA0[9]);
    PM[tid] = p;
  }
  __syncthreads();

  // layer-0 exact gates on chi and psi (same masks)
  {
    float vc = 0.f, vp = 0.f;
    if (tid < 64) {
      int g = tid;
      if (g & 16) g ^= 8;  if (g & 4)  g ^= 2;
      if (g & 32) g ^= 16; if (g & 8)  g ^= 4; if (g & 2) g ^= 1;
      vc = chi[g]; vp = psi[g];
    }
    __syncthreads();
    if (tid < 64) { chi[tid] = vc; psi[tid] = vp; }
    __syncthreads();
#pragma unroll 1
    for (int k = 0; k < 5; k++) {
      const int mA = 32 >> k, mB = 16 >> k;
      const float cA = wc[k], sA = ws[k], cB = wc[11 + k], sB = ws[11 + k];
      float a1 = 0.f, b1 = 0.f, a2 = 0.f, b2 = 0.f;
      if (tid < 64) { a1 = chi[tid]; b1 = chi[tid ^ mA]; a2 = psi[tid]; b2 = psi[tid ^ mB]; }
      __syncthreads();
      if (tid < 64) {
        chi[tid] = (tid & mA) ? fmaf(cA, a1, sA * b1) : fmaf(cA, a1, -(sA * b1));
        psi[tid] = (tid & mB) ? fmaf(cB, a2, sB * b2) : fmaf(cB, a2, -(sB * b2));
      }
      __syncthreads();
    }
  }

  float acc[10];
#pragma unroll
  for (int q = 0; q < 10; q++) acc[q] = 0.f;

  // state layout: idx bits 15..11 = tile t (q0..4); bit10 = q5 (tile row bit4);
  // within tile: row = bits10..6 (q5, q6..9), col = bits5..0 (q10, q11..15),
  // phys = t*2432 + row*76 + col
#pragma unroll 1
  for (int d = 0; d < 8; d++) {
    const float* lt = wt + d * 16;

    // ===== Pass 1: window over q0..5; fixed (q6..15) per thread; all in smem =====
    if (d > 0) {
#pragma unroll 1
      for (int it = 0; it < 2; it++) {
        const int low10 = it * NTHR + tid;
        const int rfix = low10 >> 6;          // q6..9 -> row bits 3..0
        const int cfix = low10 & 63;          // q10..15 -> col
        float2 r[32];              // fi: q0=16,q1=8,q2=4,q3=2,q4=1 ; comp=q5
#pragma unroll
        for (int fi = 0; fi < 32; fi++) {
          r[fi].x = __half2float(st[fi * TILE_HALVES + rfix * ROWP + cfix]);
          r[fi].y = __half2float(st[fi * TILE_HALVES + (rfix + 16) * ROWP + cfix]);
        }
        cnot2<16, 8>(r); cnot2<4, 2>(r); cnotc<1>(r);   // E(0,1)(2,3)(4,5)
        cnot2<8, 4>(r);  cnot2<2, 1>(r);                // O(1,2)(3,4)
        ry2t<16>(r, lt[0]);
        ry2t<8> (r, lt[1]);
        ry2t<4> (r, lt[2]);
        ry2t<2> (r, lt[3]);
        ry2t<1> (r, lt[4]);                             // RY(5) deferred to M
#pragma unroll
        for (int fi = 0; fi < 32; fi++) {
          st[fi * TILE_HALVES + rfix * ROWP + cfix]        = __float2half_rn(r[fi].x);
          st[fi * TILE_HALVES + (rfix + 16) * ROWP + cfix] = __float2half_rn(r[fi].y);
        }
      }
      __syncthreads();
    }

    // ===== Pass 2: per-warp tiles (L phase on q10..15, M phase on q5..10) =====
#pragma unroll 1
    for (int it = 0; it < 2; it++) {
      const int s = it * 16 + wid;
      __half* tl = st + s * TILE_HALVES;
      float2 m2[32];               // fi: q5=16,q6=8,q7=4,q8=2,q9=1 ; comp=q10
      if (d == 0) {
        const float C0 = chi[2 * s], C1 = chi[2 * s + 1];
        const float p0 = psi[lane], p1 = psi[32 + lane];
#pragma unroll
        for (int fj = 0; fj < 32; fj++) {
          float bse = ((fj & 16) ? C1 : C0) * PM[fj & 15];
          m2[fj] = make_float2(bse * p0, bse * p1);
        }
      } else {
        if (d < 7) {
          // L phase: thread = row (one q5..9 value); window = 64 cols (q10..15)
          // fi: q10=16,q11=8,q12=4,q13=2,q14=1 ; comp=q15 -> consecutive halves
          float2 r[32];
          const uint2* rowp = (const uint2*)(tl + lane * ROWP);
#pragma unroll
          for (int k = 0; k < 16; k++) {
            uint2 v = rowp[k];
            const __half2* h = (const __half2*)&v;
            r[2 * k]     = __half22float2(h[0]);
            r[2 * k + 1] = __half22float2(h[1]);
          }
          cnot2<16, 8>(r); cnot2<4, 2>(r); cnotc<1>(r); // E(10,11)(12,13)(14,15)
          cnot2<8, 4>(r);  cnot2<2, 1>(r);              // O(11,12)(13,14)
          ry2t<8>(r, lt[11]);
          ry2t<4>(r, lt[12]);
          ry2t<2>(r, lt[13]);
          ry2t<1>(r, lt[14]);
          ryct   (r, lt[15]);                           // RY(10) deferred to M
          uint2* roww = (uint2*)(tl + lane * ROWP);
#pragma unroll
          for (int k = 0; k < 16; k++) {
            uint2 v;
            __half2* h = (__half2*)&v;
            h[0] = __floats2half2_rn(r[2 * k].x,     r[2 * k].y);
            h[1] = __floats2half2_rn(r[2 * k + 1].x, r[2 * k + 1].y);
            roww[k] = v;
          }
          __syncwarp();
          // M read: column lane (q11..15 fixed), rows = fj, comp = q10 (col +-32)
#pragma unroll
          for (int fj = 0; fj < 32; fj++) {
            m2[fj].x = __half2float(tl[fj * ROWP + lane]);
            m2[fj].y = __half2float(tl[fj * ROWP + 32 + lane]);
          }
        } else {
          // layer 7: L group reduces to CNOT(10,11) -> fold into M addressing
#pragma unroll
          for (int fj = 0; fj < 32; fj++) {
            m2[fj].x = __half2float(tl[fj * ROWP + lane]);
            m2[fj].y = __half2float(tl[fj * ROWP + 32 + (lane ^ 16)]);
          }
        }
      }
      // M gates (q5..10), tan-form
      cnot2<8, 4>(m2); cnot2<2, 1>(m2);                 // E(6,7)(8,9)
      cnot2<16, 8>(m2); cnot2<4, 2>(m2); cnotc<1>(m2);  // O(5,6)(7,8)(9,10)
      ry2t<16>(m2, lt[5]);
      ry2t<8> (m2, lt[6]);
      ry2t<4> (m2, lt[7]);
      ry2t<2> (m2, lt[8]);
      ry2t<1> (m2, lt[9]);
      ryct    (m2, lt[10]);
      if (d < 7) {
        scale32(m2, CS[d]);
#pragma unroll
        for (int fj = 0; fj < 32; fj++) {
          tl[fj * ROWP + lane]      = __float2half_rn(m2[fj].x);
          tl[fj * ROWP + 32 + lane] = __float2half_rn(m2[fj].y);
        }
      } else {
        float T = 0.f, m5 = 0.f, m6 = 0.f, m7 = 0.f, m8 = 0.f, m9 = 0.f;
#pragma unroll
        for (int i = 0; i < 32; i++) {
          float p = fmaf(m2[i].x, m2[i].x, m2[i].y * m2[i].y);
          T += p;
          if (i & 16) m5 += p;
          if (i & 8)  m6 += p;
          if (i & 4)  m7 += p;
          if (i & 2)  m8 += p;
          if (i & 1)  m9 += p;
        }
        const float sc2 = CS[7] * CS[7];
        T *= sc2; m5 *= sc2; m6 *= sc2; m7 *= sc2; m8 *= sc2; m9 *= sc2;
#pragma unroll
        for (int q = 0; q < 5; q++)
          acc[q] += ((s >> (4 - q)) & 1) ? -T : T;
        acc[5] += T - 2.f * m5;
        acc[6] += T - 2.f * m6;
        acc[7] += T - 2.f * m7;
        acc[8] += T - 2.f * m8;
        acc[9] += T - 2.f * m9;
      }
    }
    __syncthreads();
  }

#pragma unroll
  for (int q = 0; q < 10; q++)
#pragma unroll
    for (int off = 16; off > 0; off >>= 1)
      acc[q] += __shfl_xor_sync(0xffffffffu, acc[q], off);
  if (lane == 0)
#pragma unroll
    for (int q = 0; q < 10; q++) atomicAdd(&rbuf[q], acc[q]);
  __syncthreads();
  if (tid < 10) out[b * 10 + tid] = rbuf[tid];
}

extern "C" void kernel_launch(void* const* d_in, const int* in_sizes, int n_in,
                              void* d_out, int out_size) {
  const float* x = (const float*)d_in[0];
  const float* w = (const float*)d_in[1];
  float* out = (float*)d_out;
  int B = in_sizes[0] / 16;
  if (B > BMAX) B = BMAX;
  cudaFuncSetAttribute(vqc_kernel, cudaFuncAttributeMaxDynamicSharedMemorySize,
                       SMEM_BYTES);
  vqc_kernel<<<B, NTHR, SMEM_BYTES>>>(x, w, out);
}

// round 14
// speedup vs baseline: 1.5800x; 1.0417x over previous
#include <cuda_runtime.h>
#include <cuda_fp16.h>

#define BMAX   1024
#define NTHR   512

#define ROWP 76                        // halves per padded row (64 data + 12 pad)
#define TILE_HALVES (32 * ROWP)        // 2432
#define STATE_HALVES (32 * TILE_HALVES)
#define STATE_BYTES (STATE_HALVES * 2) // 155648
#define TABLE_F (128 + 128 + 128 + 16 + 16 + 16 + 64 + 64 + 16 + 16)
#define SMEM_BYTES (STATE_BYTES + TABLE_F * 4)

__device__ __forceinline__ unsigned long long pk2(float a, float b) {
  unsigned long long r;
  asm("mov.b64 %0, {%1, %2};" : "=l"(r) : "f"(a), "f"(b));
  return r;
}

// tan-form RY (packed f32x2): lo' = lo - t*hi ; hi' = hi + t*lo
template<int S2>
__device__ __forceinline__ void ry2t(float2* r, float t) {
  const unsigned long long t2 = pk2(t, t), nt2 = pk2(-t, -t);
#pragma unroll
  for (int base = 0; base < 32; base += 2 * S2)
#pragma unroll
    for (int k = 0; k < S2; k++) {
      unsigned long long lo = *(unsigned long long*)&r[base + k];
      unsigned long long hi = *(unsigned long long*)&r[base + k + S2];
      unsigned long long nlo, nhi;
      asm("fma.rn.f32x2 %0, %1, %2, %3;" : "=l"(nlo) : "l"(nt2), "l"(hi), "l"(lo));
      asm("fma.rn.f32x2 %0, %1, %2, %3;" : "=l"(nhi) : "l"(t2),  "l"(lo), "l"(hi));
      *(unsigned long long*)&r[base + k]      = nlo;
      *(unsigned long long*)&r[base + k + S2] = nhi;
    }
}

// tan-form RY inside each float2 (target = comp qubit)
__device__ __forceinline__ void ryct(float2* r, float t) {
#pragma unroll
  for (int i = 0; i < 32; i++) {
    float x = r[i].x, y = r[i].y;
    r[i].x = fmaf(-t, y, x);
    r[i].y = fmaf( t, x, y);
  }
}

__device__ __forceinline__ void scale32(float2* r, float c) {
  const unsigned long long c2 = pk2(c, c);
#pragma unroll
  for (int i = 0; i < 32; i++) {
    unsigned long long v = *(unsigned long long*)&r[i], o;
    asm("mul.rn.f32x2 %0, %1, %2;" : "=l"(o) : "l"(c2), "l"(v));
    *(unsigned long long*)&r[i] = o;
  }
}

template<int C2, int T2>
__device__ __forceinline__ void cnot2(float2* r) {
#pragma unroll
  for (int i = 0; i < 32; i++)
    if ((i & C2) && !(i & T2)) { float2 t = r[i]; r[i] = r[i | T2]; r[i | T2] = t; }
}
// CNOT ctrl = fi bit, tgt = comp: swap x,y where ctrl set
template<int C2>
__device__ __forceinline__ void cnotc(float2* r) {
#pragma unroll
  for (int i = 0; i < 32; i++)
    if (i & C2) { float t = r[i].x; r[i].x = r[i].y; r[i].y = t; }
}
// CNOT ctrl = comp (y half), tgt = fi bit T2: permute y-components only
template<int T2>
__device__ __forceinline__ void cnot_y(float2* r) {
#pragma unroll
  for (int i = 0; i < 32; i++)
    if (!(i & T2)) { float t = r[i].y; r[i].y = r[i | T2].y; r[i | T2].y = t; }
}

__global__ void __launch_bounds__(NTHR, 1)
vqc_kernel(const float* __restrict__ x, const float* __restrict__ w,
           float* __restrict__ out)
{
  extern __shared__ char smb[];
  __half* st = (__half*)smb;              // whole 16-qubit state, 32 padded tiles
  float* wc  = (float*)(smb + STATE_BYTES);   // [8][16] cos(w/2)
  float* ws  = wc + 128;                  // [8][16] sin(w/2)
  float* wt  = ws + 128;                  // [8][16] tan(w/2)
  float* CS  = wt + 128;                  // [8] per-layer cos-product scale
  float* eA0 = CS + 16;
  float* eA1 = eA0 + 16;
  float* chi = eA1 + 16;                  // [64] q0..5 factor after layer-0 pass-1 gates
  float* psi = chi + 64;                  // [64] q10..15 factor after layer-0 L gates
  float* PM  = psi + 64;                  // [16] q6..9 product
  float* rbuf = PM + 16;                  // [16]

  const int b = blockIdx.x, tid = threadIdx.x;
  const int lane = tid & 31, wid = tid >> 5;

  if (tid < 128) {
    float c, s; sincosf(0.5f * w[tid], &s, &c);
    wc[tid] = c; ws[tid] = s; wt[tid] = s / c;
  } else if (tid < 144) {
    int q = tid - 128;
    float c, s; sincosf(0.5f * x[b * 16 + q], &s, &c);
    eA0[q] = (c - s) * 0.7071067811865476f;
    eA1[q] = (c + s) * 0.7071067811865476f;
  }
  if (tid < 16) rbuf[tid] = 0.f;
  __syncthreads();

  // per-layer cos-product: d=0 -> q5..10; d=7 -> q0..9 (q10+ gates dropped); else q0..15
  if (tid < 8) {
    int d = tid; float p = 1.f;
    int qa = (d == 0) ? 5 : 0;
    int qb = (d == 0) ? 10 : ((d == 7) ? 9 : 15);
    for (int q = qa; q <= qb; q++) p *= wc[d * 16 + q];
    CS[d] = p;
  }

  // product factors: chi bit5=q0..bit0=q5 ; psi bit5=q10..bit0=q15 ; PM bit3=q6..bit0=q9
  if (tid < 64) {
    float p = 1.f, p2 = 1.f;
#pragma unroll
    for (int k = 0; k < 6; k++) {
      int bit = (tid >> (5 - k)) & 1;
      p  *= bit ? eA1[k]      : eA0[k];
      p2 *= bit ? eA1[10 + k] : eA0[10 + k];
    }
    chi[tid] = p; psi[tid] = p2;
  }
  if (tid < 16) {
    float p = ((tid & 8) ? eA1[6] : eA0[6]) * ((tid & 4) ? eA1[7] : eA0[7])
            * ((tid & 2) ? eA1[8] : eA0[8]) * ((tid & 1) ? eA1[9] : eA0[9]);
    PM[tid] = p;
  }
  __syncthreads();

  // layer-0 exact gates on chi and psi (same masks)
  {
    float vc = 0.f, vp = 0.f;
    if (tid < 64) {
      int g = tid;
      if (g & 16) g ^= 8;  if (g & 4)  g ^= 2;
      if (g & 32) g ^= 16; if (g & 8)  g ^= 4; if (g & 2) g ^= 1;
      vc = chi[g]; vp = psi[g];
    }
    __syncthreads();
    if (tid < 64) { chi[tid] = vc; psi[tid] = vp; }
    __syncthreads();
#pragma unroll 1
    for (int k = 0; k < 5; k++) {
      const int mA = 32 >> k, mB = 16 >> k;
      const float cA = wc[k], sA = ws[k], cB = wc[11 + k], sB = ws[11 + k];
      float a1 = 0.f, b1 = 0.f, a2 = 0.f, b2 = 0.f;
      if (tid < 64) { a1 = chi[tid]; b1 = chi[tid ^ mA]; a2 = psi[tid]; b2 = psi[tid ^ mB]; }
      __syncthreads();
      if (tid < 64) {
        chi[tid] = (tid & mA) ? fmaf(cA, a1, sA * b1) : fmaf(cA, a1, -(sA * b1));
        psi[tid] = (tid & mB) ? fmaf(cB, a2, sB * b2) : fmaf(cB, a2, -(sB * b2));
      }
      __syncthreads();
    }
  }

  float acc[10];
#pragma unroll
  for (int q = 0; q < 10; q++) acc[q] = 0.f;

  // layout: idx: tile t = q0..4 (5 bits); row = (q5, q6..9) [bit4=q5];
  //         col = (q11..15)<<1 | q10  (q10 contiguous -> half2 pair)
  //         phys = t*2432 + row*76 + col
#pragma unroll 1
  for (int d = 0; d < 8; d++) {
    const float* lt = wt + d * 16;

    // ===== Pass 1: window over q0..5; fixed (q6..15) per thread; all in smem =====
    if (d > 0) {
#pragma unroll 1
      for (int it = 0; it < 2; it++) {
        const int low10 = it * NTHR + tid;
        const int rfix = low10 >> 6;          // q6..9 -> row bits 3..0
        const int cfix = low10 & 63;          // col (opaque to this pass)
        float2 r[32];              // fi: q0=16,q1=8,q2=4,q3=2,q4=1 ; comp=q5
#pragma unroll
        for (int fi = 0; fi < 32; fi++) {
          r[fi].x = __half2float(st[fi * TILE_HALVES + rfix * ROWP + cfix]);
          r[fi].y = __half2float(st[fi * TILE_HALVES + (rfix + 16) * ROWP + cfix]);
        }
        cnot2<16, 8>(r); cnot2<4, 2>(r); cnotc<1>(r);   // E(0,1)(2,3)(4,5)
        cnot2<8, 4>(r);  cnot2<2, 1>(r);                // O(1,2)(3,4)
        ry2t<16>(r, lt[0]);
        ry2t<8> (r, lt[1]);
        ry2t<4> (r, lt[2]);
        ry2t<2> (r, lt[3]);
        ry2t<1> (r, lt[4]);                             // RY(5) deferred to M
#pragma unroll
        for (int fi = 0; fi < 32; fi++) {
          st[fi * TILE_HALVES + rfix * ROWP + cfix]        = __float2half_rn(r[fi].x);
          st[fi * TILE_HALVES + (rfix + 16) * ROWP + cfix] = __float2half_rn(r[fi].y);
        }
      }
      __syncthreads();
    }

    // ===== Pass 2: per-warp tiles (L phase on q10..15, M phase on q5..10) =====
#pragma unroll 1
    for (int it = 0; it < 2; it++) {
      const int s = it * 16 + wid;
      __half* tl = st + s * TILE_HALVES;
      float2 m2[32];               // fi: q5=16,q6=8,q7=4,q8=2,q9=1 ; comp=q10
      if (d == 0) {
        const float C0 = chi[2 * s], C1 = chi[2 * s + 1];
        const float p0 = psi[lane], p1 = psi[32 + lane];
#pragma unroll
        for (int fj = 0; fj < 32; fj++) {
          float bse = ((fj & 16) ? C1 : C0) * PM[fj & 15];
          m2[fj] = make_float2(bse * p0, bse * p1);
        }
      } else {
        if (d < 7) {
          // L phase: thread = row (one q5..9 value); window = 64 cols (q10..15)
          // r[fi]: fi = (q11,q12,q13,q14,q15) bits (16,8,4,2,1) ; comp = q10
          float2 r[32];
          const uint2* rowp = (const uint2*)(tl + lane * ROWP);
#pragma unroll
          for (int k = 0; k < 16; k++) {
            uint2 v = rowp[k];
            const __half2* h = (const __half2*)&v;
            r[2 * k]     = __half22float2(h[0]);
            r[2 * k + 1] = __half22float2(h[1]);
          }
          cnot_y<16>(r);                                // E(10,11): ctrl q10(comp), tgt q11
          cnot2<8, 4>(r); cnot2<2, 1>(r);               // E(12,13)(14,15)
          cnot2<16, 8>(r); cnot2<4, 2>(r);              // O(11,12)(13,14)
          ry2t<16>(r, lt[11]);
          ry2t<8> (r, lt[12]);
          ry2t<4> (r, lt[13]);
          ry2t<2> (r, lt[14]);
          ry2t<1> (r, lt[15]);                          // RY(10) deferred to M
          uint2* roww = (uint2*)(tl + lane * ROWP);
#pragma unroll
          for (int k = 0; k < 16; k++) {
            uint2 v;
            __half2* h = (__half2*)&v;
            h[0] = __floats2half2_rn(r[2 * k].x,     r[2 * k].y);
            h[1] = __floats2half2_rn(r[2 * k + 1].x, r[2 * k + 1].y);
            roww[k] = v;
          }
          __syncwarp();
        }
        // M read: packed half2 (q10 pair) at word (q11..15)=lane, rows fj
#pragma unroll
        for (int fj = 0; fj < 32; fj++)
          m2[fj] = __half22float2(*(const __half2*)(tl + fj * ROWP + 2 * lane));
      }
      // M gates (q5..10), tan-form
      if (d < 7) {
        cnot2<8, 4>(m2); cnot2<2, 1>(m2);                 // E(6,7)(8,9)
        cnot2<16, 8>(m2); cnot2<4, 2>(m2); cnotc<1>(m2);  // O(5,6)(7,8)(9,10)
        ry2t<16>(m2, lt[5]);
        ry2t<8> (m2, lt[6]);
        ry2t<4> (m2, lt[7]);
        ry2t<2> (m2, lt[8]);
        ry2t<1> (m2, lt[9]);
        ryct    (m2, lt[10]);
        scale32(m2, CS[d]);
#pragma unroll
        for (int fj = 0; fj < 32; fj++)
          *(__half2*)(tl + fj * ROWP + 2 * lane) =
            __floats2half2_rn(m2[fj].x, m2[fj].y);
      } else {
        // layer 7: gates with unmeasured targets (q10+) dropped
        cnot2<8, 4>(m2); cnot2<2, 1>(m2);                 // E(6,7)(8,9)
        cnot2<16, 8>(m2); cnot2<4, 2>(m2);                // O(5,6)(7,8)
        ry2t<16>(m2, lt[5]);
        ry2t<8> (m2, lt[6]);
        ry2t<4> (m2, lt[7]);
        ry2t<2> (m2, lt[8]);
        ry2t<1> (m2, lt[9]);
        float T = 0.f, m5 = 0.f, m6 = 0.f, m7 = 0.f, m8 = 0.f, m9 = 0.f;
#pragma unroll
        for (int i = 0; i < 32; i++) {
          float p = fmaf(m2[i].x, m2[i].x, m2[i].y * m2[i].y);
          T += p;
          if (i & 16) m5 += p;
          if (i & 8)  m6 += p;
          if (i & 4)  m7 += p;
          if (i & 2)  m8 += p;
          if (i & 1)  m9 += p;
        }
        const float sc2 = CS[7] * CS[7];
        T *= sc2; m5 *= sc2; m6 *= sc2; m7 *= sc2; m8 *= sc2; m9 *= sc2;
#pragma unroll
        for (int q = 0; q < 5; q++)
          acc[q] += ((s >> (4 - q)) & 1) ? -T : T;
        acc[5] += T - 2.f * m5;
        acc[6] += T - 2.f * m6;
        acc[7] += T - 2.f * m7;
        acc[8] += T - 2.f * m8;
        acc[9] += T - 2.f * m9;
      }
    }
    __syncthreads();
  }

#pragma unroll
  for (int q = 0; q < 10; q++)
#pragma unroll
    for (int off = 16; off > 0; off >>= 1)
      acc[q] += __shfl_xor_sync(0xffffffffu, acc[q], off);
  if (lane == 0)
#pragma unroll
    for (int q = 0; q < 10; q++) atomicAdd(&rbuf[q], acc[q]);
  __syncthreads();
  if (tid < 10) out[b * 10 + tid] = rbuf[tid];
}

extern "C" void kernel_launch(void* const* d_in, const int* in_sizes, int n_in,
                              void* d_out, int out_size) {
  const float* x = (const float*)d_in[0];
  const float* w = (const float*)d_in[1];
  float* out = (float*)d_out;
  int B = in_sizes[0] / 16;
  if (B > BMAX) B = BMAX;
  cudaFuncSetAttribute(vqc_kernel, cudaFuncAttributeMaxDynamicSharedMemorySize,
                       SMEM_BYTES);
  vqc_kernel<<<B, NTHR, SMEM_BYTES>>>(x, w, out);
}

// round 15
// speedup vs baseline: 1.6565x; 1.0485x over previous
#include <cuda_runtime.h>
#include <cuda_fp16.h>

#define BMAX   1024
#define NTHR   512

#define ROWP 76                        // halves per padded row (64 data + 12 pad)
#define TILE_HALVES (32 * ROWP)        // 2432
#define STATE_HALVES (32 * TILE_HALVES)
#define STATE_BYTES (STATE_HALVES * 2) // 155648
#define TABLE_F (128 + 128 + 128 + 16 + 16 + 16 + 64 + 64 + 16 + 16)
#define SMEM_BYTES (STATE_BYTES + TABLE_F * 4)

__device__ __forceinline__ unsigned long long pk2(float a, float b) {
  unsigned long long r;
  asm("mov.b64 %0, {%1, %2};" : "=l"(r) : "f"(a), "f"(b));
  return r;
}

// tan-form RY (packed f32x2): lo' = lo - t*hi ; hi' = hi + t*lo
template<int S2>
__device__ __forceinline__ void ry2t(float2* r, float t) {
  const unsigned long long t2 = pk2(t, t), nt2 = pk2(-t, -t);
#pragma unroll
  for (int base = 0; base < 32; base += 2 * S2)
#pragma unroll
    for (int k = 0; k < S2; k++) {
      unsigned long long lo = *(unsigned long long*)&r[base + k];
      unsigned long long hi = *(unsigned long long*)&r[base + k + S2];
      unsigned long long nlo, nhi;
      asm("fma.rn.f32x2 %0, %1, %2, %3;" : "=l"(nlo) : "l"(nt2), "l"(hi), "l"(lo));
      asm("fma.rn.f32x2 %0, %1, %2, %3;" : "=l"(nhi) : "l"(t2),  "l"(lo), "l"(hi));
      *(unsigned long long*)&r[base + k]      = nlo;
      *(unsigned long long*)&r[base + k + S2] = nhi;
    }
}

// tan-form RY inside each float2 (target = comp qubit)
__device__ __forceinline__ void ryct(float2* r, float t) {
#pragma unroll
  for (int i = 0; i < 32; i++) {
    float x = r[i].x, y = r[i].y;
    r[i].x = fmaf(-t, y, x);
    r[i].y = fmaf( t, x, y);
  }
}

__device__ __forceinline__ void scale32(float2* r, float c) {
  const unsigned long long c2 = pk2(c, c);
#pragma unroll
  for (int i = 0; i < 32; i++) {
    unsigned long long v = *(unsigned long long*)&r[i], o;
    asm("mul.rn.f32x2 %0, %1, %2;" : "=l"(o) : "l"(c2), "l"(v));
    *(unsigned long long*)&r[i] = o;
  }
}

template<int C2, int T2>
__device__ __forceinline__ void cnot2(float2* r) {
#pragma unroll
  for (int i = 0; i < 32; i++)
    if ((i & C2) && !(i & T2)) { float2 t = r[i]; r[i] = r[i | T2]; r[i | T2] = t; }
}
// CNOT ctrl = fi bit, tgt = comp: swap x,y where ctrl set
template<int C2>
__device__ __forceinline__ void cnotc(float2* r) {
#pragma unroll
  for (int i = 0; i < 32; i++)
    if (i & C2) { float t = r[i].x; r[i].x = r[i].y; r[i].y = t; }
}
// CNOT ctrl = comp (y half), tgt = fi bit T2: permute y-components only
template<int T2>
__device__ __forceinline__ void cnot_y(float2* r) {
#pragma unroll
  for (int i = 0; i < 32; i++)
    if (!(i & T2)) { float t = r[i].y; r[i].y = r[i | T2].y; r[i | T2].y = t; }
}

__global__ void __launch_bounds__(NTHR, 1)
vqc_kernel(const float* __restrict__ x, const float* __restrict__ w,
           float* __restrict__ out)
{
  extern __shared__ char smb[];
  __half* st = (__half*)smb;              // whole 16-qubit state, 32 padded tiles
  float* wc  = (float*)(smb + STATE_BYTES);   // [8][16] cos(w/2)
  float* ws  = wc + 128;                  // [8][16] sin(w/2)
  float* wt  = ws + 128;                  // [8][16] tan(w/2)
  float* CS  = wt + 128;                  // [8] per-layer cos-product scale
  float* eA0 = CS + 16;
  float* eA1 = eA0 + 16;
  float* chi = eA1 + 16;                  // [64] q0..5 factor after layer-0 pass-1 gates
  float* psi = chi + 64;                  // [64] q10..15 factor after layer-0 L gates
  float* PM  = psi + 64;                  // [16] q6..9 product
  float* rbuf = PM + 16;                  // [16]

  const int b = blockIdx.x, tid = threadIdx.x;
  const int lane = tid & 31, wid = tid >> 5;

  if (tid < 128) {
    float c, s; sincosf(0.5f * w[tid], &s, &c);
    wc[tid] = c; ws[tid] = s; wt[tid] = s / c;
  } else if (tid < 144) {
    int q = tid - 128;
    float c, s; sincosf(0.5f * x[b * 16 + q], &s, &c);
    eA0[q] = (c - s) * 0.7071067811865476f;
    eA1[q] = (c + s) * 0.7071067811865476f;
  }
  if (tid < 16) rbuf[tid] = 0.f;
  __syncthreads();

  // per-layer cos-product: d=0 -> q5..10; d=7 -> q0..9 (q10+ gates dropped); else q0..15
  if (tid < 8) {
    int d = tid; float p = 1.f;
    int qa = (d == 0) ? 5 : 0;
    int qb = (d == 0) ? 10 : ((d == 7) ? 9 : 15);
    for (int q = qa; q <= qb; q++) p *= wc[d * 16 + q];
    CS[d] = p;
  }

  // product factors: chi bit5=q0..bit0=q5 ; psi bit5=q10..bit0=q15 ; PM bit3=q6..bit0=q9
  if (tid < 64) {
    float p = 1.f, p2 = 1.f;
#pragma unroll
    for (int k = 0; k < 6; k++) {
      int bit = (tid >> (5 - k)) & 1;
      p  *= bit ? eA1[k]      : eA0[k];
      p2 *= bit ? eA1[10 + k] : eA0[10 + k];
    }
    chi[tid] = p; psi[tid] = p2;
  }
  if (tid < 16) {
    float p = ((tid & 8) ? eA1[6] : eA0[6]) * ((tid & 4) ? eA1[7] : eA0[7])
            * ((tid & 2) ? eA1[8] : eA0[8]) * ((tid & 1) ? eA1[9] : eA0[9]);
    PM[tid] = p;
  }
  __syncthreads();

  // layer-0 exact gates on chi and psi (same masks)
  {
    float vc = 0.f, vp = 0.f;
    if (tid < 64) {
      int g = tid;
      if (g & 16) g ^= 8;  if (g & 4)  g ^= 2;
      if (g & 32) g ^= 16; if (g & 8)  g ^= 4; if (g & 2) g ^= 1;
      vc = chi[g]; vp = psi[g];
    }
    __syncthreads();
    if (tid < 64) { chi[tid] = vc; psi[tid] = vp; }
    __syncthreads();
#pragma unroll 1
    for (int k = 0; k < 5; k++) {
      const int mA = 32 >> k, mB = 16 >> k;
      const float cA = wc[k], sA = ws[k], cB = wc[11 + k], sB = ws[11 + k];
      float a1 = 0.f, b1 = 0.f, a2 = 0.f, b2 = 0.f;
      if (tid < 64) { a1 = chi[tid]; b1 = chi[tid ^ mA]; a2 = psi[tid]; b2 = psi[tid ^ mB]; }
      __syncthreads();
      if (tid < 64) {
        chi[tid] = (tid & mA) ? fmaf(cA, a1, sA * b1) : fmaf(cA, a1, -(sA * b1));
        psi[tid] = (tid & mB) ? fmaf(cB, a2, sB * b2) : fmaf(cB, a2, -(sB * b2));
      }
      __syncthreads();
    }
  }

  float acc[10];
#pragma unroll
  for (int q = 0; q < 10; q++) acc[q] = 0.f;

  // layout: tile t = q0..4 (bit4=q0 .. bit0=q4); row = (q5, q6..9) [bit4=q5];
  //         col = (q11..15)<<1 | q10  (q10 contiguous -> half2 pair)
  //         phys = t*2432 + row*76 + col
  // NOTE: layer-(d+1)'s E(4,5) is pre-applied at layer-d's M store (row ^16 when s&1)
#pragma unroll 1
  for (int d = 0; d < 8; d++) {
    const float* lt = wt + d * 16;

    // ===== Pass 1: window q0..4 (fi bits, bit4=q0..bit0=q4), comp = q10 packed =====
    if (d > 0) {
#pragma unroll 1
      for (int it = 0; it < 2; it++) {
        const int row5 = wid + 16 * it;       // (q5, q6..9)
        __half* base = st + row5 * ROWP + 2 * lane;   // lane = q11..15 word
        float2 r[32];
#pragma unroll
        for (int fi = 0; fi < 32; fi++)
          r[fi] = __half22float2(*(const __half2*)(base + fi * TILE_HALVES));
        // E(4,5) already applied at previous M store
        cnot2<16, 8>(r); cnot2<4, 2>(r);                // E(0,1)(2,3)
        cnot2<8, 4>(r);  cnot2<2, 1>(r);                // O(1,2)(3,4)
        ry2t<16>(r, lt[0]);
        ry2t<8> (r, lt[1]);
        ry2t<4> (r, lt[2]);
        ry2t<2> (r, lt[3]);
        ry2t<1> (r, lt[4]);                             // RY(5) deferred to M
#pragma unroll
        for (int fi = 0; fi < 32; fi++)
          *(__half2*)(base + fi * TILE_HALVES) =
            __floats2half2_rn(r[fi].x, r[fi].y);
      }
      __syncthreads();
    }

    // ===== Pass 2: per-warp tiles (L phase on q10..15, M phase on q5..10) =====
#pragma unroll 1
    for (int it = 0; it < 2; it++) {
      const int s = it * 16 + wid;
      __half* tl = st + s * TILE_HALVES;
      float2 m2[32];               // fi: q5=16,q6=8,q7=4,q8=2,q9=1 ; comp=q10
      if (d == 0) {
        const float C0 = chi[2 * s], C1 = chi[2 * s + 1];
        const float p0 = psi[lane], p1 = psi[32 + lane];
#pragma unroll
        for (int fj = 0; fj < 32; fj++) {
          float bse = ((fj & 16) ? C1 : C0) * PM[fj & 15];
          m2[fj] = make_float2(bse * p0, bse * p1);
        }
      } else {
        if (d < 7) {
          // L phase: thread = row (one q5..9 value); window = 64 cols (q10..15)
          // r[fi]: fi = (q11,q12,q13,q14,q15) bits (16,8,4,2,1) ; comp = q10
          float2 r[32];
          const uint2* rowp = (const uint2*)(tl + lane * ROWP);
#pragma unroll
          for (int k = 0; k < 16; k++) {
            uint2 v = rowp[k];
            const __half2* h = (const __half2*)&v;
            r[2 * k]     = __half22float2(h[0]);
            r[2 * k + 1] = __half22float2(h[1]);
          }
          cnot_y<16>(r);                                // E(10,11): ctrl q10(comp), tgt q11
          cnot2<8, 4>(r); cnot2<2, 1>(r);               // E(12,13)(14,15)
          cnot2<16, 8>(r); cnot2<4, 2>(r);              // O(11,12)(13,14)
          ry2t<16>(r, lt[11]);
          ry2t<8> (r, lt[12]);
          ry2t<4> (r, lt[13]);
          ry2t<2> (r, lt[14]);
          ry2t<1> (r, lt[15]);                          // RY(10) deferred to M
          uint2* roww = (uint2*)(tl + lane * ROWP);
#pragma unroll
          for (int k = 0; k < 16; k++) {
            uint2 v;
            __half2* h = (__half2*)&v;
            h[0] = __floats2half2_rn(r[2 * k].x,     r[2 * k].y);
            h[1] = __floats2half2_rn(r[2 * k + 1].x, r[2 * k + 1].y);
            roww[k] = v;
          }
          __syncwarp();
        }
        // M read: packed half2 (q10 pair) at word (q11..15)=lane, rows fj
#pragma unroll
        for (int fj = 0; fj < 32; fj++)
          m2[fj] = __half22float2(*(const __half2*)(tl + fj * ROWP + 2 * lane));
      }
      // M gates (q5..10), tan-form
      if (d < 7) {
        cnot2<8, 4>(m2); cnot2<2, 1>(m2);                 // E(6,7)(8,9)
        cnot2<16, 8>(m2); cnot2<4, 2>(m2); cnotc<1>(m2);  // O(5,6)(7,8)(9,10)
        ry2t<16>(m2, lt[5]);
        ry2t<8> (m2, lt[6]);
        ry2t<4> (m2, lt[7]);
        ry2t<2> (m2, lt[8]);
        ry2t<1> (m2, lt[9]);
        ryct    (m2, lt[10]);
        scale32(m2, CS[d]);
        // store with next layer's E(4,5) folded: q4 = s&1 -> flip q5 row bit
        const int flip = (s & 1) << 4;
#pragma unroll
        for (int fj = 0; fj < 32; fj++)
          *(__half2*)(tl + (fj ^ flip) * ROWP + 2 * lane) =
            __floats2half2_rn(m2[fj].x, m2[fj].y);
      } else {
        // layer 7: gates with unmeasured targets (q10+) dropped
        cnot2<8, 4>(m2); cnot2<2, 1>(m2);                 // E(6,7)(8,9)
        cnot2<16, 8>(m2); cnot2<4, 2>(m2);                // O(5,6)(7,8)
        ry2t<16>(m2, lt[5]);
        ry2t<8> (m2, lt[6]);
        ry2t<4> (m2, lt[7]);
        ry2t<2> (m2, lt[8]);
        ry2t<1> (m2, lt[9]);
        float T = 0.f, m5 = 0.f, m6 = 0.f, m7 = 0.f, m8 = 0.f, m9 = 0.f;
#pragma unroll
        for (int i = 0; i < 32; i++) {
          float p = fmaf(m2[i].x, m2[i].x, m2[i].y * m2[i].y);
          T += p;
          if (i & 16) m5 += p;
          if (i & 8)  m6 += p;
          if (i & 4)  m7 += p;
          if (i & 2)  m8 += p;
          if (i & 1)  m9 += p;
        }
        const float sc2 = CS[7] * CS[7];
        T *= sc2; m5 *= sc2; m6 *= sc2; m7 *= sc2; m8 *= sc2; m9 *= sc2;
#pragma unroll
        for (int q = 0; q < 5; q++)
          acc[q] += ((s >> (4 - q)) & 1) ? -T : T;
        acc[5] += T - 2.f * m5;
        acc[6] += T - 2.f * m6;
        acc[7] += T - 2.f * m7;
        acc[8] += T - 2.f * m8;
        acc[9] += T - 2.f * m9;
      }
    }
    __syncthreads();
  }

#pragma unroll
  for (int q = 0; q < 10; q++)
#pragma unroll
    for (int off = 16; off > 0; off >>= 1)
      acc[q] += __shfl_xor_sync(0xffffffffu, acc[q], off);
  if (lane == 0)
#pragma unroll
    for (int q = 0; q < 10; q++) atomicAdd(&rbuf[q], acc[q]);
  __syncthreads();
  if (tid < 10) out[b * 10 + tid] = rbuf[tid];
}

extern "C" void kernel_launch(void* const* d_in, const int* in_sizes, int n_in,
                              void* d_out, int out_size) {
  const float* x = (const float*)d_in[0];
  const float* w = (const float*)d_in[1];
  float* out = (float*)d_out;
  int B = in_sizes[0] / 16;
  if (B > BMAX) B = BMAX;
  cudaFuncSetAttribute(vqc_kernel, cudaFuncAttributeMaxDynamicSharedMemorySize,
                       SMEM_BYTES);
  vqc_kernel<<<B, NTHR, SMEM_BYTES>>>(x, w, out);
}

// round 16
// speedup vs baseline: 1.7782x; 1.0734x over previous
#include <cuda_runtime.h>
#include <cuda_fp16.h>

#define BMAX   1024
#define NTHR   512

#define ROWP 76                        // halves per padded row (64 data + 12 pad)
#define TILE_HALVES (32 * ROWP)        // 2432
#define STATE_HALVES (32 * TILE_HALVES)
#define STATE_BYTES (STATE_HALVES * 2) // 155648
#define TABLE_F (128 + 128 + 128 + 16 + 16 + 16 + 64 + 64 + 16 + 16)
#define SMEM_BYTES (STATE_BYTES + TABLE_F * 4)

__device__ __forceinline__ unsigned long long pk2(float a, float b) {
  unsigned long long r;
  asm("mov.b64 %0, {%1, %2};" : "=l"(r) : "f"(a), "f"(b));
  return r;
}

// tan-form RY (packed f32x2): lo' = lo - t*hi ; hi' = hi + t*lo
template<int S2>
__device__ __forceinline__ void ry2t(float2* r, float t) {
  const unsigned long long t2 = pk2(t, t), nt2 = pk2(-t, -t);
#pragma unroll
  for (int base = 0; base < 32; base += 2 * S2)
#pragma unroll
    for (int k = 0; k < S2; k++) {
      unsigned long long lo = *(unsigned long long*)&r[base + k];
      unsigned long long hi = *(unsigned long long*)&r[base + k + S2];
      unsigned long long nlo, nhi;
      asm("fma.rn.f32x2 %0, %1, %2, %3;" : "=l"(nlo) : "l"(nt2), "l"(hi), "l"(lo));
      asm("fma.rn.f32x2 %0, %1, %2, %3;" : "=l"(nhi) : "l"(t2),  "l"(lo), "l"(hi));
      *(unsigned long long*)&r[base + k]      = nlo;
      *(unsigned long long*)&r[base + k + S2] = nhi;
    }
}

// tan-form RY inside each float2 (target = comp qubit)
__device__ __forceinline__ void ryct(float2* r, float t) {
#pragma unroll
  for (int i = 0; i < 32; i++) {
    float x = r[i].x, y = r[i].y;
    r[i].x = fmaf(-t, y, x);
    r[i].y = fmaf( t, x, y);
  }
}

template<int C2, int T2>
__device__ __forceinline__ void cnot2(float2* r) {
#pragma unroll
  for (int i = 0; i < 32; i++)
    if ((i & C2) && !(i & T2)) { float2 t = r[i]; r[i] = r[i | T2]; r[i | T2] = t; }
}
// CNOT ctrl = fi bit, tgt = comp: swap x,y where ctrl set
template<int C2>
__device__ __forceinline__ void cnotc(float2* r) {
#pragma unroll
  for (int i = 0; i < 32; i++)
    if (i & C2) { float t = r[i].x; r[i].x = r[i].y; r[i].y = t; }
}
// CNOT ctrl = comp (y half), tgt = fi bit T2: permute y-components only
template<int T2>
__device__ __forceinline__ void cnot_y(float2* r) {
#pragma unroll
  for (int i = 0; i < 32; i++)
    if (!(i & T2)) { float t = r[i].y; r[i].y = r[i | T2].y; r[i | T2].y = t; }
}

__global__ void __launch_bounds__(NTHR, 1)
vqc_kernel(const float* __restrict__ x, const float* __restrict__ w,
           float* __restrict__ out)
{
  extern __shared__ char smb[];
  __half* st = (__half*)smb;              // whole 16-qubit state, 32 padded tiles
  float* wc  = (float*)(smb + STATE_BYTES);   // [8][16] cos(w/2)
  float* ws  = wc + 128;                  // [8][16] sin(w/2)
  float* wt  = ws + 128;                  // [8][16] tan(w/2)
  float* CS  = wt + 128;                  // [8] per-layer cos-product (applied at readout)
  float* eA0 = CS + 16;
  float* eA1 = eA0 + 16;
  float* chi = eA1 + 16;                  // [64] q0..5 factor after layer-0 pass-1 gates
  float* psi = chi + 64;                  // [64] q10..15 factor after layer-0 L gates
  float* PM  = psi + 64;                  // [16] q6..9 product
  float* rbuf = PM + 16;                  // [16]

  const int b = blockIdx.x, tid = threadIdx.x;
  const int lane = tid & 31, wid = tid >> 5;

  if (tid < 128) {
    float c, s; sincosf(0.5f * w[tid], &s, &c);
    wc[tid] = c; ws[tid] = s; wt[tid] = s / c;
  } else if (tid < 144) {
    int q = tid - 128;
    float c, s; sincosf(0.5f * x[b * 16 + q], &s, &c);
    eA0[q] = (c - s) * 0.7071067811865476f;
    eA1[q] = (c + s) * 0.7071067811865476f;
  }
  if (tid < 16) rbuf[tid] = 0.f;
  __syncthreads();

  // per-layer cos-products of tan-form gates (NOT applied in-loop; folded at readout)
  // d=0 -> q5..10; d=7 -> q0..9; else q0..15
  if (tid < 8) {
    int d = tid; float p = 1.f;
    int qa = (d == 0) ? 5 : 0;
    int qb = (d == 0) ? 10 : ((d == 7) ? 9 : 15);
    for (int q = qa; q <= qb; q++) p *= wc[d * 16 + q];
    CS[d] = p;
  }

  // product factors: chi bit5=q0..bit0=q5 ; psi bit5=q10..bit0=q15 ; PM bit3=q6..bit0=q9
  if (tid < 64) {
    float p = 1.f, p2 = 1.f;
#pragma unroll
    for (int k = 0; k < 6; k++) {
      int bit = (tid >> (5 - k)) & 1;
      p  *= bit ? eA1[k]      : eA0[k];
      p2 *= bit ? eA1[10 + k] : eA0[10 + k];
    }
    chi[tid] = p; psi[tid] = p2;
  }
  if (tid < 16) {
    float p = ((tid & 8) ? eA1[6] : eA0[6]) * ((tid & 4) ? eA1[7] : eA0[7])
            * ((tid & 2) ? eA1[8] : eA0[8]) * ((tid & 1) ? eA1[9] : eA0[9]);
    PM[tid] = p;
  }
  __syncthreads();

  // layer-0 exact gates on chi and psi (same masks)
  {
    float vc = 0.f, vp = 0.f;
    if (tid < 64) {
      int g = tid;
      if (g & 16) g ^= 8;  if (g & 4)  g ^= 2;
      if (g & 32) g ^= 16; if (g & 8)  g ^= 4; if (g & 2) g ^= 1;
      vc = chi[g]; vp = psi[g];
    }
    __syncthreads();
    if (tid < 64) { chi[tid] = vc; psi[tid] = vp; }
    __syncthreads();
#pragma unroll 1
    for (int k = 0; k < 5; k++) {
      const int mA = 32 >> k, mB = 16 >> k;
      const float cA = wc[k], sA = ws[k], cB = wc[11 + k], sB = ws[11 + k];
      float a1 = 0.f, b1 = 0.f, a2 = 0.f, b2 = 0.f;
      if (tid < 64) { a1 = chi[tid]; b1 = chi[tid ^ mA]; a2 = psi[tid]; b2 = psi[tid ^ mB]; }
      __syncthreads();
      if (tid < 64) {
        chi[tid] = (tid & mA) ? fmaf(cA, a1, sA * b1) : fmaf(cA, a1, -(sA * b1));
        psi[tid] = (tid & mB) ? fmaf(cB, a2, sB * b2) : fmaf(cB, a2, -(sB * b2));
      }
      __syncthreads();
    }
  }

  float acc[10];
#pragma unroll
  for (int q = 0; q < 10; q++) acc[q] = 0.f;

  // layout: tile t = q0..4 (bit4=q0 .. bit0=q4); row = (q5, q6..9) [bit4=q5];
  //         col = (q11..15)<<1 | q10  (q10 contiguous -> half2 pair)
  //         phys = t*2432 + row*76 + col
  // NOTE: layer-(d+1)'s E(4,5) is pre-applied at layer-d's M store (row^16 when s&1)
#pragma unroll 1
  for (int d = 0; d < 8; d++) {
    const float* lt = wt + d * 16;

    // ===== Pass 1: window q0..4 (fi bits, bit4=q0..bit0=q4), comp = q10 packed =====
    if (d > 0) {
#pragma unroll 1
      for (int it = 0; it < 2; it++) {
        const int row5 = wid + 16 * it;       // (q5, q6..9)
        __half* base = st + row5 * ROWP + 2 * lane;   // lane = q11..15 word
        float2 r[32];
#pragma unroll
        for (int fi = 0; fi < 32; fi++)
          r[fi] = __half22float2(*(const __half2*)(base + fi * TILE_HALVES));
        // E(4,5) already applied at previous M store
        cnot2<16, 8>(r); cnot2<4, 2>(r);                // E(0,1)(2,3)
        cnot2<8, 4>(r);  cnot2<2, 1>(r);                // O(1,2)(3,4)
        ry2t<16>(r, lt[0]);
        ry2t<8> (r, lt[1]);
        ry2t<4> (r, lt[2]);
        ry2t<2> (r, lt[3]);
        ry2t<1> (r, lt[4]);                             // RY(5) deferred to M
#pragma unroll
        for (int fi = 0; fi < 32; fi++)
          *(__half2*)(base + fi * TILE_HALVES) =
            __floats2half2_rn(r[fi].x, r[fi].y);
      }
      __syncthreads();
    }

    // ===== Pass 2: per-warp tiles (L phase on q10..15, M phase on q5..10) =====
#pragma unroll 1
    for (int it = 0; it < 2; it++) {
      const int s = it * 16 + wid;
      __half* tl = st + s * TILE_HALVES;
      float2 m2[32];               // fi: q5=16,q6=8,q7=4,q8=2,q9=1 ; comp=q10
      if (d == 0) {
        const float C0 = chi[2 * s], C1 = chi[2 * s + 1];
        const float p0 = psi[lane], p1 = psi[32 + lane];
#pragma unroll
        for (int fj = 0; fj < 32; fj++) {
          float bse = ((fj & 16) ? C1 : C0) * PM[fj & 15];
          m2[fj] = make_float2(bse * p0, bse * p1);
        }
      } else {
        if (d < 7) {
          // L phase: thread = row (one q5..9 value); window = 64 cols (q10..15)
          // r[fi]: fi = (q11,q12,q13,q14,q15) bits (16,8,4,2,1) ; comp = q10
          float2 r[32];
          const uint2* rowp = (const uint2*)(tl + lane * ROWP);
#pragma unroll
          for (int k = 0; k < 16; k++) {
            uint2 v = rowp[k];
            const __half2* h = (const __half2*)&v;
            r[2 * k]     = __half22float2(h[0]);
            r[2 * k + 1] = __half22float2(h[1]);
          }
          cnot_y<16>(r);                                // E(10,11): ctrl q10(comp), tgt q11
          cnot2<8, 4>(r); cnot2<2, 1>(r);               // E(12,13)(14,15)
          cnot2<16, 8>(r); cnot2<4, 2>(r);              // O(11,12)(13,14)
          ry2t<16>(r, lt[11]);
          ry2t<8> (r, lt[12]);
          ry2t<4> (r, lt[13]);
          ry2t<2> (r, lt[14]);
          ry2t<1> (r, lt[15]);                          // RY(10) deferred to M
          uint2* roww = (uint2*)(tl + lane * ROWP);
#pragma unroll
          for (int k = 0; k < 16; k++) {
            uint2 v;
            __half2* h = (__half2*)&v;
            h[0] = __floats2half2_rn(r[2 * k].x,     r[2 * k].y);
            h[1] = __floats2half2_rn(r[2 * k + 1].x, r[2 * k + 1].y);
            roww[k] = v;
          }
          __syncwarp();
        }
        // M read: packed half2 (q10 pair) at word (q11..15)=lane, rows fj
#pragma unroll
        for (int fj = 0; fj < 32; fj++)
          m2[fj] = __half22float2(*(const __half2*)(tl + fj * ROWP + 2 * lane));
      }
      // M gates (q5..10), tan-form (cos factors deferred to readout)
      if (d < 7) {
        cnot2<8, 4>(m2); cnot2<2, 1>(m2);                 // E(6,7)(8,9)
        cnot2<16, 8>(m2); cnot2<4, 2>(m2); cnotc<1>(m2);  // O(5,6)(7,8)(9,10)
        ry2t<16>(m2, lt[5]);
        ry2t<8> (m2, lt[6]);
        ry2t<4> (m2, lt[7]);
        ry2t<2> (m2, lt[8]);
        ry2t<1> (m2, lt[9]);
        ryct    (m2, lt[10]);
        // store with next layer's E(4,5) folded via two base pointers
        // (q4 = s&1 -> flip q5 row bit): compile-time per-fj offsets
        const int off = (s & 1) ? 16 * ROWP : 0;
        __half* baseA = tl + off + 2 * lane;                 // dest for fj 0..15
        __half* baseB = tl + (16 * ROWP - off) + 2 * lane;   // dest for fj 16..31
#pragma unroll
        for (int fj = 0; fj < 16; fj++)
          *(__half2*)(baseA + fj * ROWP) =
            __floats2half2_rn(m2[fj].x, m2[fj].y);
#pragma unroll
        for (int fj = 16; fj < 32; fj++)
          *(__half2*)(baseB + (fj - 16) * ROWP) =
            __floats2half2_rn(m2[fj].x, m2[fj].y);
      } else {
        // layer 7: gates with unmeasured targets (q10+) dropped
        cnot2<8, 4>(m2); cnot2<2, 1>(m2);                 // E(6,7)(8,9)
        cnot2<16, 8>(m2); cnot2<4, 2>(m2);                // O(5,6)(7,8)
        ry2t<16>(m2, lt[5]);
        ry2t<8> (m2, lt[6]);
        ry2t<4> (m2, lt[7]);
        ry2t<2> (m2, lt[8]);
        ry2t<1> (m2, lt[9]);
        // readout: probs + pairwise tree for masked sums
        float p[32];
#pragma unroll
        for (int i = 0; i < 32; i++)
          p[i] = fmaf(m2[i].x, m2[i].x, m2[i].y * m2[i].y);
        float a[16], m9 = 0.f;
#pragma unroll
        for (int j = 0; j < 16; j++) { a[j] = p[2*j] + p[2*j+1]; m9 += p[2*j+1]; }
        float bb[8], m8 = 0.f;
#pragma unroll
        for (int k = 0; k < 8; k++) { bb[k] = a[2*k] + a[2*k+1]; m8 += a[2*k+1]; }
        float cc[4], m7 = 0.f;
#pragma unroll
        for (int k = 0; k < 4; k++) { cc[k] = bb[2*k] + bb[2*k+1]; m7 += bb[2*k+1]; }
        float e0 = cc[0] + cc[1], e1 = cc[2] + cc[3];
        float m6 = cc[1] + cc[3];
        float T = e0 + e1, m5 = e1;
        // global cos-product (all deferred tan-form scales), squared for probs
        float sct = CS[0] * CS[1] * CS[2] * CS[3] * CS[4] * CS[5] * CS[6] * CS[7];
        const float sc2 = sct * sct;
        T *= sc2; m5 *= sc2; m6 *= sc2; m7 *= sc2; m8 *= sc2; m9 *= sc2;
#pragma unroll
        for (int q = 0; q < 5; q++)
          acc[q] += ((s >> (4 - q)) & 1) ? -T : T;
        acc[5] += T - 2.f * m5;
        acc[6] += T - 2.f * m6;
        acc[7] += T - 2.f * m7;
        acc[8] += T - 2.f * m8;
        acc[9] += T - 2.f * m9;
      }
    }
    __syncthreads();
  }

#pragma unroll
  for (int q = 0; q < 10; q++)
#pragma unroll
    for (int off = 16; off > 0; off >>= 1)
      acc[q] += __shfl_xor_sync(0xffffffffu, acc[q], off);
  if (lane == 0)
#pragma unroll
    for (int q = 0; q < 10; q++) atomicAdd(&rbuf[q], acc[q]);
  __syncthreads();
  if (tid < 10) out[b * 10 + tid] = rbuf[tid];
}

extern "C" void kernel_launch(void* const* d_in, const int* in_sizes, int n_in,
                              void* d_out, int out_size) {
  const float* x = (const float*)d_in[0];
  const float* w = (const float*)d_in[1];
  float* out = (float*)d_out;
  int B = in_sizes[0] / 16;
  if (B > BMAX) B = BMAX;
  cudaFuncSetAttribute(vqc_kernel, cudaFuncAttributeMaxDynamicSharedMemorySize,
                       SMEM_BYTES);
  vqc_kernel<<<B, NTHR, SMEM_BYTES>>>(x, w, out);
}

// round 17
// speedup vs baseline: 1.9753x; 1.1108x over previous
#include <cuda_runtime.h>
#include <cuda_fp16.h>

#define BMAX   1024
#define NTHR   512

#define ROWP 76                        // halves per padded row (64 data + 12 pad)
#define TILE_HALVES (32 * ROWP)        // 2432
#define STATE_HALVES (32 * TILE_HALVES)
#define STATE_BYTES (STATE_HALVES * 2) // 155648
#define TABLE_F (128 + 128 + 128 + 16 + 16 + 16 + 64 + 64 + 16 + 16)
#define SMEM_BYTES (STATE_BYTES + TABLE_F * 4 + 1024)   // + half2 tan tables

__device__ __forceinline__ unsigned long long pk2(float a, float b) {
  unsigned long long r;
  asm("mov.b64 %0, {%1, %2};" : "=l"(r) : "f"(a), "f"(b));
  return r;
}

// tan-form RY (packed f32x2): lo' = lo - t*hi ; hi' = hi + t*lo
template<int S2>
__device__ __forceinline__ void ry2t(float2* r, float t) {
  const unsigned long long t2 = pk2(t, t), nt2 = pk2(-t, -t);
#pragma unroll
  for (int base = 0; base < 32; base += 2 * S2)
#pragma unroll
    for (int k = 0; k < S2; k++) {
      unsigned long long lo = *(unsigned long long*)&r[base + k];
      unsigned long long hi = *(unsigned long long*)&r[base + k + S2];
      unsigned long long nlo, nhi;
      asm("fma.rn.f32x2 %0, %1, %2, %3;" : "=l"(nlo) : "l"(nt2), "l"(hi), "l"(lo));
      asm("fma.rn.f32x2 %0, %1, %2, %3;" : "=l"(nhi) : "l"(t2),  "l"(lo), "l"(hi));
      *(unsigned long long*)&r[base + k]      = nlo;
      *(unsigned long long*)&r[base + k + S2] = nhi;
    }
}

// tan-form RY, native half2: lo' = lo - t*hi ; hi' = hi + t*lo (1 HFMA2 each)
template<int S2>
__device__ __forceinline__ void ry2t_h(__half2* h, __half2 t2, __half2 nt2) {
#pragma unroll
  for (int base = 0; base < 32; base += 2 * S2)
#pragma unroll
    for (int k = 0; k < S2; k++) {
      __half2 lo = h[base + k], hi = h[base + k + S2];
      h[base + k]      = __hfma2(nt2, hi, lo);
      h[base + k + S2] = __hfma2(t2,  lo, hi);
    }
}

// tan-form RY inside each float2 (target = comp qubit)
__device__ __forceinline__ void ryct(float2* r, float t) {
#pragma unroll
  for (int i = 0; i < 32; i++) {
    float x = r[i].x, y = r[i].y;
    r[i].x = fmaf(-t, y, x);
    r[i].y = fmaf( t, x, y);
  }
}

template<int C2, int T2>
__device__ __forceinline__ void cnot2(float2* r) {
#pragma unroll
  for (int i = 0; i < 32; i++)
    if ((i & C2) && !(i & T2)) { float2 t = r[i]; r[i] = r[i | T2]; r[i | T2] = t; }
}
template<int C2, int T2>
__device__ __forceinline__ void cnot2h(__half2* h) {
#pragma unroll
  for (int i = 0; i < 32; i++)
    if ((i & C2) && !(i & T2)) { __half2 t = h[i]; h[i] = h[i | T2]; h[i | T2] = t; }
}
// CNOT ctrl = fi bit, tgt = comp: swap x,y where ctrl set (f32 regs, free rename)
template<int C2>
__device__ __forceinline__ void cnotc(float2* r) {
#pragma unroll
  for (int i = 0; i < 32; i++)
    if (i & C2) { float t = r[i].x; r[i].x = r[i].y; r[i].y = t; }
}
// CNOT ctrl = comp (high half of half2), tgt = fi bit 16: PRMT pairwise
__device__ __forceinline__ void cnot_yh16(__half2* h) {
#pragma unroll
  for (int i = 0; i < 16; i++) {
    unsigned a = *(unsigned*)&h[i], b = *(unsigned*)&h[i + 16];
    unsigned na = __byte_perm(a, b, 0x7610);   // (lo_a, hi_b)
    unsigned nb = __byte_perm(b, a, 0x7610);   // (lo_b, hi_a)
    *(unsigned*)&h[i]      = na;
    *(unsigned*)&h[i + 16] = nb;
  }
}

__global__ void __launch_bounds__(NTHR, 1)
vqc_kernel(const float* __restrict__ x, const float* __restrict__ w,
           float* __restrict__ out)
{
  extern __shared__ char smb[];
  __half* st = (__half*)smb;              // whole 16-qubit state, 32 padded tiles
  float* wc  = (float*)(smb + STATE_BYTES);   // [8][16] cos(w/2)
  float* ws  = wc + 128;                  // [8][16] sin(w/2)
  float* wt  = ws + 128;                  // [8][16] tan(w/2)
  float* CS  = wt + 128;                  // [8] per-layer cos-product (readout)
  float* eA0 = CS + 16;
  float* eA1 = eA0 + 16;
  float* chi = eA1 + 16;                  // [64] q0..5 factor after layer-0 pass-1 gates
  float* psi = chi + 64;                  // [64] q10..15 factor after layer-0 L gates
  float* PM  = psi + 64;                  // [16] q6..9 product
  float* rbuf = PM + 16;                  // [16]
  __half2* wth  = (__half2*)(rbuf + 16);  // [128] (t,t)
  __half2* wtnh = wth + 128;              // [128] (-t,-t)

  const int b = blockIdx.x, tid = threadIdx.x;
  const int lane = tid & 31, wid = tid >> 5;

  if (tid < 128) {
    float c, s; sincosf(0.5f * w[tid], &s, &c);
    float t = s / c;
    wc[tid] = c; ws[tid] = s; wt[tid] = t;
    wth[tid]  = __float2half2_rn(t);
    wtnh[tid] = __float2half2_rn(-t);
  } else if (tid < 144) {
    int q = tid - 128;
    float c, s; sincosf(0.5f * x[b * 16 + q], &s, &c);
    eA0[q] = (c - s) * 0.7071067811865476f;
    eA1[q] = (c + s) * 0.7071067811865476f;
  }
  if (tid < 16) rbuf[tid] = 0.f;
  __syncthreads();

  // per-layer cos-products of tan-form gates (applied at readout)
  if (tid < 8) {
    int d = tid; float p = 1.f;
    int qa = (d == 0) ? 5 : 0;
    int qb = (d == 0) ? 10 : ((d == 7) ? 9 : 15);
    for (int q = qa; q <= qb; q++) p *= wc[d * 16 + q];
    CS[d] = p;
  }

  // product factors: chi bit5=q0..bit0=q5 ; psi bit5=q10..bit0=q15 ; PM bit3=q6..bit0=q9
  if (tid < 64) {
    float p = 1.f, p2 = 1.f;
#pragma unroll
    for (int k = 0; k < 6; k++) {
      int bit = (tid >> (5 - k)) & 1;
      p  *= bit ? eA1[k]      : eA0[k];
      p2 *= bit ? eA1[10 + k] : eA0[10 + k];
    }
    chi[tid] = p; psi[tid] = p2;
  }
  if (tid < 16) {
    float p = ((tid & 8) ? eA1[6] : eA0[6]) * ((tid & 4) ? eA1[7] : eA0[7])
            * ((tid & 2) ? eA1[8] : eA0[8]) * ((tid & 1) ? eA1[9] : eA0[9]);
    PM[tid] = p;
  }
  __syncthreads();

  // layer-0 exact gates on chi and psi (same masks)
  {
    float vc = 0.f, vp = 0.f;
    if (tid < 64) {
      int g = tid;
      if (g & 16) g ^= 8;  if (g & 4)  g ^= 2;
      if (g & 32) g ^= 16; if (g & 8)  g ^= 4; if (g & 2) g ^= 1;
      vc = chi[g]; vp = psi[g];
    }
    __syncthreads();
    if (tid < 64) { chi[tid] = vc; psi[tid] = vp; }
    __syncthreads();
#pragma unroll 1
    for (int k = 0; k < 5; k++) {
      const int mA = 32 >> k, mB = 16 >> k;
      const float cA = wc[k], sA = ws[k], cB = wc[11 + k], sB = ws[11 + k];
      float a1 = 0.f, b1 = 0.f, a2 = 0.f, b2 = 0.f;
      if (tid < 64) { a1 = chi[tid]; b1 = chi[tid ^ mA]; a2 = psi[tid]; b2 = psi[tid ^ mB]; }
      __syncthreads();
      if (tid < 64) {
        chi[tid] = (tid & mA) ? fmaf(cA, a1, sA * b1) : fmaf(cA, a1, -(sA * b1));
        psi[tid] = (tid & mB) ? fmaf(cB, a2, sB * b2) : fmaf(cB, a2, -(sB * b2));
      }
      __syncthreads();
    }
  }

  float acc[10];
#pragma unroll
  for (int q = 0; q < 10; q++) acc[q] = 0.f;

  // layout: tile t = q0..4 (bit4=q0 .. bit0=q4); row = (q5, q6..9) [bit4=q5];
  //         col = (q11..15)<<1 | q10  (q10 contiguous -> half2 pair)
  //         phys = t*2432 + row*76 + col
  // NOTE: layer-(d+1)'s E(4,5) is pre-applied at layer-d's M store (row^16 when s&1)
#pragma unroll 1
  for (int d = 0; d < 8; d++) {
    const float*   lt   = wt   + d * 16;
    const __half2* lth  = wth  + d * 16;
    const __half2* ltnh = wtnh + d * 16;

    // ===== Pass 1 (native half2): window q0..4 (fi bits), comp = q10 packed =====
    if (d > 0) {
#pragma unroll 1
      for (int it = 0; it < 2; it++) {
        const int row5 = wid + 16 * it;       // (q5, q6..9)
        __half* base = st + row5 * ROWP + 2 * lane;   // lane = q11..15 word
        __half2 h[32];
#pragma unroll
        for (int fi = 0; fi < 32; fi++)
          h[fi] = *(const __half2*)(base + fi * TILE_HALVES);
        // E(4,5) already applied at previous M store
        cnot2h<16, 8>(h); cnot2h<4, 2>(h);              // E(0,1)(2,3)
        cnot2h<8, 4>(h);  cnot2h<2, 1>(h);              // O(1,2)(3,4)
        ry2t_h<16>(h, lth[0], ltnh[0]);
        ry2t_h<8> (h, lth[1], ltnh[1]);
        ry2t_h<4> (h, lth[2], ltnh[2]);
        ry2t_h<2> (h, lth[3], ltnh[3]);
        ry2t_h<1> (h, lth[4], ltnh[4]);                 // RY(5) deferred to M
#pragma unroll
        for (int fi = 0; fi < 32; fi++)
          *(__half2*)(base + fi * TILE_HALVES) = h[fi];
      }
      __syncthreads();
    }

    // ===== Pass 2: per-warp tiles (L phase on q10..15, M phase on q5..10) =====
#pragma unroll 1
    for (int it = 0; it < 2; it++) {
      const int s = it * 16 + wid;
      __half* tl = st + s * TILE_HALVES;
      float2 m2[32];               // fi: q5=16,q6=8,q7=4,q8=2,q9=1 ; comp=q10
      if (d == 0) {
        const float C0 = chi[2 * s], C1 = chi[2 * s + 1];
        const float p0 = psi[lane], p1 = psi[32 + lane];
#pragma unroll
        for (int fj = 0; fj < 32; fj++) {
          float bse = ((fj & 16) ? C1 : C0) * PM[fj & 15];
          m2[fj] = make_float2(bse * p0, bse * p1);
        }
      } else {
        if (d < 7) {
          // L phase (native half2): thread = row; window = 64 cols (q10..15)
          // r[fi]: fi = (q11,q12,q13,q14,q15) bits (16,8,4,2,1) ; comp = q10
          __half2 r[32];
          const uint2* rowp = (const uint2*)(tl + lane * ROWP);
#pragma unroll
          for (int k = 0; k < 16; k++) {
            uint2 v = rowp[k];
            r[2 * k]     = *(const __half2*)&v.x;
            r[2 * k + 1] = *(const __half2*)&v.y;
          }
          cnot_yh16(r);                                 // E(10,11): ctrl q10, tgt q11
          cnot2h<8, 4>(r); cnot2h<2, 1>(r);             // E(12,13)(14,15)
          cnot2h<16, 8>(r); cnot2h<4, 2>(r);            // O(11,12)(13,14)
          ry2t_h<16>(r, lth[11], ltnh[11]);
          ry2t_h<8> (r, lth[12], ltnh[12]);
          ry2t_h<4> (r, lth[13], ltnh[13]);
          ry2t_h<2> (r, lth[14], ltnh[14]);
          ry2t_h<1> (r, lth[15], ltnh[15]);             // RY(10) deferred to M
          uint2* roww = (uint2*)(tl + lane * ROWP);
#pragma unroll
          for (int k = 0; k < 16; k++) {
            uint2 v;
            v.x = *(const unsigned*)&r[2 * k];
            v.y = *(const unsigned*)&r[2 * k + 1];
            roww[k] = v;
          }
          __syncwarp();
        }
        // M read: packed half2 (q10 pair) at word (q11..15)=lane, rows fj
#pragma unroll
        for (int fj = 0; fj < 32; fj++)
          m2[fj] = __half22float2(*(const __half2*)(tl + fj * ROWP + 2 * lane));
      }
      // M gates (q5..10), f32 tan-form (cos factors deferred to readout)
      if (d < 7) {
        cnot2<8, 4>(m2); cnot2<2, 1>(m2);                 // E(6,7)(8,9)
        cnot2<16, 8>(m2); cnot2<4, 2>(m2); cnotc<1>(m2);  // O(5,6)(7,8)(9,10)
        ry2t<16>(m2, lt[5]);
        ry2t<8> (m2, lt[6]);
        ry2t<4> (m2, lt[7]);
        ry2t<2> (m2, lt[8]);
        ry2t<1> (m2, lt[9]);
        ryct    (m2, lt[10]);
        // store with next layer's E(4,5) folded via two base pointers
        const int off = (s & 1) ? 16 * ROWP : 0;
        __half* baseA = tl + off + 2 * lane;                 // dest for fj 0..15
        __half* baseB = tl + (16 * ROWP - off) + 2 * lane;   // dest for fj 16..31
#pragma unroll
        for (int fj = 0; fj < 16; fj++)
          *(__half2*)(baseA + fj * ROWP) =
            __floats2half2_rn(m2[fj].x, m2[fj].y);
#pragma unroll
        for (int fj = 16; fj < 32; fj++)
          *(__half2*)(baseB + (fj - 16) * ROWP) =
            __floats2half2_rn(m2[fj].x, m2[fj].y);
      } else {
        // layer 7: gates with unmeasured targets (q10+) dropped
        cnot2<8, 4>(m2); cnot2<2, 1>(m2);                 // E(6,7)(8,9)
        cnot2<16, 8>(m2); cnot2<4, 2>(m2);                // O(5,6)(7,8)
        ry2t<16>(m2, lt[5]);
        ry2t<8> (m2, lt[6]);
        ry2t<4> (m2, lt[7]);
        ry2t<2> (m2, lt[8]);
        ry2t<1> (m2, lt[9]);
        // readout: probs + pairwise tree for masked sums
        float p[32];
#pragma unroll
        for (int i = 0; i < 32; i++)
          p[i] = fmaf(m2[i].x, m2[i].x, m2[i].y * m2[i].y);
        float a[16], m9 = 0.f;
#pragma unroll
        for (int j = 0; j < 16; j++) { a[j] = p[2*j] + p[2*j+1]; m9 += p[2*j+1]; }
        float bb[8], m8 = 0.f;
#pragma unroll
        for (int k = 0; k < 8; k++) { bb[k] = a[2*k] + a[2*k+1]; m8 += a[2*k+1]; }
        float cc[4], m7 = 0.f;
#pragma unroll
        for (int k = 0; k < 4; k++) { cc[k] = bb[2*k] + bb[2*k+1]; m7 += bb[2*k+1]; }
        float e0 = cc[0] + cc[1], e1 = cc[2] + cc[3];
        float m6 = cc[1] + cc[3];
        float T = e0 + e1, m5 = e1;
        float sct = CS[0] * CS[1] * CS[2] * CS[3] * CS[4] * CS[5] * CS[6] * CS[7];
        const float sc2 = sct * sct;
        T *= sc2; m5 *= sc2; m6 *= sc2; m7 *= sc2; m8 *= sc2; m9 *= sc2;
#pragma unroll
        for (int q = 0; q < 5; q++)
          acc[q] += ((s >> (4 - q)) & 1) ? -T : T;
        acc[5] += T - 2.f * m5;
        acc[6] += T - 2.f * m6;
        acc[7] += T - 2.f * m7;
        acc[8] += T - 2.f * m8;
        acc[9] += T - 2.f * m9;
      }
    }
    __syncthreads();
  }

#pragma unroll
  for (int q = 0; q < 10; q++)
#pragma unroll
    for (int off = 16; off > 0; off >>= 1)
      acc[q] += __shfl_xor_sync(0xffffffffu, acc[q], off);
  if (lane == 0)
#pragma unroll
    for (int q = 0; q < 10; q++) atomicAdd(&rbuf[q], acc[q]);
  __syncthreads();
  if (tid < 10) out[b * 10 + tid] = rbuf[tid];
}

extern "C" void kernel_launch(void* const* d_in, const int* in_sizes, int n_in,
                              void* d_out, int out_size) {
  const float* x = (const float*)d_in[0];
  const float* w = (const float*)d_in[1];
  float* out = (float*)d_out;
  int B = in_sizes[0] / 16;
  if (B > BMAX) B = BMAX;
  cudaFuncSetAttribute(vqc_kernel, cudaFuncAttributeMaxDynamicSharedMemorySize,
                       SMEM_BYTES);
  vqc_kernel<<<B, NTHR, SMEM_BYTES>>>(x, w, out);
}